// round 7
// baseline (speedup 1.0000x reference)
#include <cuda_runtime.h>
#include <cuda_bf16.h>
#include <cstddef>
#include <cstdint>

// ---------------- Problem constants (fixed by the reference) ----------------
#define N_NODES 50000
#define E_EDGES 800000
#define NFEAT   512
#define NH      256
#define NL      4
#define EVO     1024

// ---------------- Device-global scratch (no allocations allowed) ------------
__device__ float g_local0[(size_t)N_NODES * NH];          // relu(x @ fc0)
__device__ float g_h[(size_t)N_NODES * NH];               // dense transform per conv layer
__device__ float g_layers[(size_t)N_NODES * NL * NH];     // concat of 4 layer outputs
__device__ float g_glob[(size_t)N_NODES * NH];            // relu(evo @ fc1)
__device__ float g_local2[(size_t)N_NODES * NH];          // relu(layers @ fc2)

__device__ int   g_counts[N_NODES];
__device__ int   g_rowptr[N_NODES + 1];
__device__ int   g_cursor[N_NODES];
__device__ int   g_colidx[E_EDGES];
__device__ float g_vals[E_EDGES];

// ---------------- CSR build kernels ----------------------------------------
__global__ void k_zero_counts() {
    int i = blockIdx.x * blockDim.x + threadIdx.x;
    if (i < N_NODES) g_counts[i] = 0;
}

__global__ void k_hist(const int* __restrict__ dst) {
    int e = blockIdx.x * blockDim.x + threadIdx.x;
    if (e < E_EDGES) atomicAdd(&g_counts[dst[e]], 1);
}

// Single-block exclusive scan (warp-shuffle two-level, 3 syncs per chunk).
__global__ void k_scan() {
    __shared__ int warp_sums[32];
    __shared__ int s_carry;
    const int t = threadIdx.x, lane = t & 31, wid = t >> 5;
    if (t == 0) s_carry = 0;
    __syncthreads();
    for (int base = 0; base < N_NODES; base += 1024) {
        const int i = base + t;
        const int v = (i < N_NODES) ? g_counts[i] : 0;
        int x = v;
#pragma unroll
        for (int d = 1; d < 32; d <<= 1) {
            int y = __shfl_up_sync(0xFFFFFFFFu, x, d);
            if (lane >= d) x += y;
        }
        if (lane == 31) warp_sums[wid] = x;
        __syncthreads();
        if (wid == 0) {
            int w = warp_sums[lane];
            int ws = w;
#pragma unroll
            for (int d = 1; d < 32; d <<= 1) {
                int y = __shfl_up_sync(0xFFFFFFFFu, ws, d);
                if (lane >= d) ws += y;
            }
            warp_sums[lane] = ws - w;
        }
        __syncthreads();
        const int ex = x - v + warp_sums[wid];
        const int carry = s_carry;
        if (i < N_NODES) {
            g_rowptr[i] = carry + ex;
            g_cursor[i] = carry + ex;
        }
        __syncthreads();
        if (t == 1023) s_carry = carry + ex + v;
        __syncthreads();
    }
    if (threadIdx.x == 0) g_rowptr[N_NODES] = s_carry;
}

__global__ void k_scatter(const int* __restrict__ src, const int* __restrict__ dst,
                          const float* __restrict__ w) {
    int e = blockIdx.x * blockDim.x + threadIdx.x;
    if (e < E_EDGES) {
        int d = dst[e];
        int pos = atomicAdd(&g_cursor[d], 1);
        g_colidx[pos] = src[e];
        g_vals[pos]   = w[e];
    }
}

// ---------------- TF32 tensor-core GEMM (cp.async 3-stage pipeline) ---------
// C[M,256] = A[M,K] @ B[K,256] (+bias)(+relu), optional concat-A2 at k=256.
// BM=128, BN=128, BK=32, 256 threads = 8 warps (2m x 4n), warp tile 64x32.
// smem holds fp32; cvt to tf32 at fragment-load. mma.sync.m16n8k8.

__device__ __forceinline__ uint32_t f2tf32(float x) {
    uint32_t u;
    asm("cvt.rna.tf32.f32 %0, %1;" : "=r"(u) : "f"(x));
    return u;
}

__device__ __forceinline__ void mma_tf32(float* d, const uint32_t* a, const uint32_t* b) {
    asm volatile(
        "mma.sync.aligned.m16n8k8.row.col.f32.tf32.tf32.f32 "
        "{%0,%1,%2,%3}, {%4,%5,%6,%7}, {%8,%9}, {%0,%1,%2,%3};\n"
        : "+f"(d[0]), "+f"(d[1]), "+f"(d[2]), "+f"(d[3])
        : "r"(a[0]), "r"(a[1]), "r"(a[2]), "r"(a[3]), "r"(b[0]), "r"(b[1]));
}

__device__ __forceinline__ void cp16(uint32_t dst_s, const void* src, bool valid) {
    int sz = valid ? 16 : 0;
    asm volatile("cp.async.cg.shared.global [%0], [%1], 16, %2;\n"
                 :: "r"(dst_s), "l"(src), "r"(sz));
}

#define GEMM_BM 128
#define GEMM_BN 128
#define GEMM_BK 32
#define GEMM_PA 36      // A frag bank = (4g+q) mod 32 : bijection, conflict-free
#define GEMM_PB 136     // B frag bank = (8q+g) mod 32 : bijection, conflict-free
#define GEMM_STAGES 3
#define GEMM_STG_U32 (GEMM_BM * GEMM_PA + GEMM_BK * GEMM_PB)
#define GEMM_SMEM (GEMM_STAGES * GEMM_STG_U32 * 4)

template <bool RELU, bool CONCAT>
__global__ __launch_bounds__(256, 2) void tf32gemm(
    const float* __restrict__ A, int lda, int K,
    const float* __restrict__ A2,           // CONCAT: second source at k>=256 (lda=256)
    const float* __restrict__ B,            // ldb fixed = 256
    const float* __restrict__ bias,         // may be nullptr
    float* __restrict__ C, int ldc, int M)
{
    constexpr int BM = GEMM_BM, BK = GEMM_BK;
    constexpr int PA = GEMM_PA, PB = GEMM_PB;
    extern __shared__ float dynsmem[];

    const int t    = threadIdx.x;
    const int lane = t & 31;
    const int warp = t >> 5;
    const int row0 = blockIdx.y * BM;
    const int col0 = blockIdx.x * GEMM_BN;
    const int m0w  = (warp & 1) * 64;
    const int n0w  = (warp >> 1) * 32;
    const int g    = lane >> 2;
    const int q    = lane & 3;

    const uint32_t smem_u = (uint32_t)__cvta_generic_to_shared(dynsmem);

    float acc[4][4][4];
#pragma unroll
    for (int mi = 0; mi < 4; mi++)
#pragma unroll
        for (int ni = 0; ni < 4; ni++)
#pragma unroll
            for (int r = 0; r < 4; r++) acc[mi][ni][r] = 0.f;

    // A loader: f = t + i*256, row = t>>3 + i*32, kq = (t&7)*4
    const int ar0 = t >> 3;
    const int akq = (t & 7) * 4;
    // B loader: f = t + i*256, row = t>>5 + i*8, nq = (t&31)*4
    const int br0 = t >> 5;
    const int bnq = (t & 31) * 4;

    auto issue = [&](int buf, int stage_idx) {
        const int k0 = stage_idx * BK;
        const uint32_t as_u = smem_u + (uint32_t)(buf * GEMM_STG_U32) * 4u;
        const uint32_t bs_u = as_u + (uint32_t)(BM * PA) * 4u;
        const float* Asel = A;
        int kbase = k0;
        if (CONCAT && k0 >= 256) { Asel = A2; kbase = k0 - 256; }
#pragma unroll
        for (int i = 0; i < 4; i++) {
            const int row = ar0 + i * 32;
            const bool valid = (row0 + row) < M;
            const int rclamp = valid ? (row0 + row) : (M - 1);
            cp16(as_u + (uint32_t)(row * PA + akq) * 4u,
                 Asel + (size_t)rclamp * lda + kbase + akq, valid);
        }
#pragma unroll
        for (int i = 0; i < 4; i++) {
            const int row = br0 + i * 8;
            cp16(bs_u + (uint32_t)(row * PB + bnq) * 4u,
                 B + (size_t)(k0 + row) * 256 + col0 + bnq, true);
        }
    };

    auto compute = [&](int buf) {
        const float* as = dynsmem + buf * GEMM_STG_U32;
        const float* bs = as + BM * PA;
#pragma unroll
        for (int kk = 0; kk < BK; kk += 8) {
            uint32_t a[4][4], b[4][2];
#pragma unroll
            for (int mi = 0; mi < 4; mi++) {
                const int mr = m0w + mi * 16 + g;
                a[mi][0] = f2tf32(as[(mr    ) * PA + kk + q    ]);
                a[mi][1] = f2tf32(as[(mr + 8) * PA + kk + q    ]);
                a[mi][2] = f2tf32(as[(mr    ) * PA + kk + q + 4]);
                a[mi][3] = f2tf32(as[(mr + 8) * PA + kk + q + 4]);
            }
#pragma unroll
            for (int ni = 0; ni < 4; ni++) {
                const int nc = n0w + ni * 8 + g;
                b[ni][0] = f2tf32(bs[(kk + q    ) * PB + nc]);
                b[ni][1] = f2tf32(bs[(kk + q + 4) * PB + nc]);
            }
#pragma unroll
            for (int mi = 0; mi < 4; mi++)
#pragma unroll
                for (int ni = 0; ni < 4; ni++)
                    mma_tf32(acc[mi][ni], a[mi], b[ni]);
        }
    };

    const int nk = K / BK;

    // Prologue: fill first STAGES-1 stages
#pragma unroll
    for (int s = 0; s < GEMM_STAGES - 1; s++) {
        if (s < nk) issue(s, s);
        asm volatile("cp.async.commit_group;\n");
    }

    // One __syncthreads per iteration:
    //   the top sync at iteration `it` is reached by every warp only AFTER it
    //   finished compute(it-1), so issuing into stage (it+2)%3 == (it-1)%3
    //   (the stage consumed at it-1) is race-free.
    for (int it = 0; it < nk; it++) {
        asm volatile("cp.async.wait_group %0;\n" :: "n"(GEMM_STAGES - 2));
        __syncthreads();
        const int nxt = it + GEMM_STAGES - 1;
        if (nxt < nk) issue(nxt % GEMM_STAGES, nxt);
        asm volatile("cp.async.commit_group;\n");
        compute(it % GEMM_STAGES);
    }

    // Epilogue: c0,c1 at (row g, col 2q,2q+1); c2,c3 at (row g+8)
#pragma unroll
    for (int mi = 0; mi < 4; mi++) {
        const int r0 = row0 + m0w + mi * 16 + g;
        const int r1 = r0 + 8;
#pragma unroll
        for (int ni = 0; ni < 4; ni++) {
            const int c = col0 + n0w + ni * 8 + q * 2;
            float bx = 0.f, by = 0.f;
            if (bias) { bx = bias[c]; by = bias[c + 1]; }
#pragma unroll
            for (int half = 0; half < 2; half++) {
                const int r = half ? r1 : r0;
                if (r < M) {
                    float vx = acc[mi][ni][half * 2 + 0] + bx;
                    float vy = acc[mi][ni][half * 2 + 1] + by;
                    if (RELU) { vx = fmaxf(vx, 0.f); vy = fmaxf(vy, 0.f); }
                    *(float2*)(C + (size_t)r * ldc + c) = make_float2(vx, vy);
                }
            }
        }
    }
}

// ---------------- SpMM + ReLU (float4, 4 rows per CTA, 4-way unroll) --------
__global__ __launch_bounds__(256) void k_spmm_relu(const float* __restrict__ h, int layer) {
    const int sub = threadIdx.x >> 6;          // 0..3 : row within block
    const int f4  = threadIdx.x & 63;          // float4 lane: 64 x 4 = 256 feats
    const int d   = blockIdx.x * 4 + sub;      // 12500 * 4 = 50000 exact
    const int beg = g_rowptr[d];
    const int end = g_rowptr[d + 1];
    const float4* h4 = (const float4*)h;
    float4 acc = make_float4(0.f, 0.f, 0.f, 0.f);

    int k = beg;
    // 4-way unroll: batch independent gathers for MLP
    for (; k + 4 <= end; k += 4) {
        const int   s0 = g_colidx[k    ], s1 = g_colidx[k + 1];
        const int   s2 = g_colidx[k + 2], s3 = g_colidx[k + 3];
        const float w0 = g_vals[k    ], w1 = g_vals[k + 1];
        const float w2 = g_vals[k + 2], w3 = g_vals[k + 3];
        float4 v0 = h4[(size_t)s0 * 64 + f4];
        float4 v1 = h4[(size_t)s1 * 64 + f4];
        float4 v2 = h4[(size_t)s2 * 64 + f4];
        float4 v3 = h4[(size_t)s3 * 64 + f4];
        acc.x += w0 * v0.x; acc.y += w0 * v0.y; acc.z += w0 * v0.z; acc.w += w0 * v0.w;
        acc.x += w1 * v1.x; acc.y += w1 * v1.y; acc.z += w1 * v1.z; acc.w += w1 * v1.w;
        acc.x += w2 * v2.x; acc.y += w2 * v2.y; acc.z += w2 * v2.z; acc.w += w2 * v2.w;
        acc.x += w3 * v3.x; acc.y += w3 * v3.y; acc.z += w3 * v3.z; acc.w += w3 * v3.w;
    }
    for (; k < end; k++) {
        const int   s = g_colidx[k];
        const float w = g_vals[k];
        float4 v = h4[(size_t)s * 64 + f4];
        acc.x += w * v.x; acc.y += w * v.y; acc.z += w * v.z; acc.w += w * v.w;
    }
    float4 r = make_float4(fmaxf(acc.x, 0.f), fmaxf(acc.y, 0.f),
                           fmaxf(acc.z, 0.f), fmaxf(acc.w, 0.f));
    ((float4*)g_layers)[(size_t)d * (NL * NH / 4) + layer * 64 + f4] = r;
}

// ---------------- Launch ----------------------------------------------------
extern "C" void kernel_launch(void* const* d_in, const int* in_sizes, int n_in,
                              void* d_out, int out_size)
{
    const float* x        = (const float*)d_in[0];   // [N, 512]
    const float* evo      = (const float*)d_in[1];   // [N, 1024]
    const int*   esrc     = (const int*)  d_in[2];   // [E]
    const int*   edst     = (const int*)  d_in[3];   // [E]
    const float* ew       = (const float*)d_in[4];   // [E]
    const float* conv_w   = (const float*)d_in[5];   // [4, 256, 256]
    const float* fc0_w    = (const float*)d_in[6];   // [512, 256]
    const float* fc0_b    = (const float*)d_in[7];
    const float* fc1_w    = (const float*)d_in[8];   // [1024, 256]
    const float* fc1_b    = (const float*)d_in[9];
    const float* fc2_w    = (const float*)d_in[10];  // [1024, 256]
    const float* fc2_b    = (const float*)d_in[11];
    const float* fc3_w    = (const float*)d_in[12];  // [512, 256]
    const float* fc3_b    = (const float*)d_in[13];
    float* out = (float*)d_out;

    float *p_local0, *p_h, *p_layers, *p_glob, *p_local2;
    cudaGetSymbolAddress((void**)&p_local0, g_local0);
    cudaGetSymbolAddress((void**)&p_h,      g_h);
    cudaGetSymbolAddress((void**)&p_layers, g_layers);
    cudaGetSymbolAddress((void**)&p_glob,   g_glob);
    cudaGetSymbolAddress((void**)&p_local2, g_local2);

    cudaFuncSetAttribute(tf32gemm<true,  false>,
                         cudaFuncAttributeMaxDynamicSharedMemorySize, GEMM_SMEM);
    cudaFuncSetAttribute(tf32gemm<false, false>,
                         cudaFuncAttributeMaxDynamicSharedMemorySize, GEMM_SMEM);
    cudaFuncSetAttribute(tf32gemm<true,  true>,
                         cudaFuncAttributeMaxDynamicSharedMemorySize, GEMM_SMEM);

    const dim3 gemm_grid(2, (N_NODES + 127) / 128);

    // Launch order chosen so ncu (-s 5, with 2 harness prelude launches)
    // captures the conv0 dense-transform GEMM instead of k_scatter.
    // Dependencies: conv0-gemm needs only fc0 output; CSR only needed by spmm.

    // (pos 0) fc0: local0 = relu(x @ fc0_w + b)
    tf32gemm<true, false><<<gemm_grid, 256, GEMM_SMEM>>>(
        x, NFEAT, NFEAT, nullptr, fc0_w, fc0_b, p_local0, NH, N_NODES);
    // (pos 1,2) CSR build begins
    k_zero_counts<<<(N_NODES + 255) / 256, 256>>>();
    k_hist<<<E_EDGES / 256, 256>>>(edst);
    // (pos 3) conv layer 0 dense transform  <-- ncu capture target
    tf32gemm<false, false><<<gemm_grid, 256, GEMM_SMEM>>>(
        p_local0, NH, NH, nullptr, conv_w, nullptr, p_h, NH, N_NODES);
    // (pos 4,5) CSR build finishes
    k_scan<<<1, 1024>>>();
    k_scatter<<<E_EDGES / 256, 256>>>(esrc, edst, ew);
    // (pos 6) spmm layer 0
    k_spmm_relu<<<N_NODES / 4, 256>>>(p_h, 0);

    // --- conv layers 1..3 ---
    for (int i = 1; i < NL; i++) {
        tf32gemm<false, false><<<gemm_grid, 256, GEMM_SMEM>>>(
            p_layers + (i - 1) * NH, NL * NH, NH,
            nullptr, conv_w + (size_t)i * NH * NH, nullptr, p_h, NH, N_NODES);
        k_spmm_relu<<<N_NODES / 4, 256>>>(p_h, i);
    }

    // --- fc2: local2 = relu(layers @ fc2_w + b) ---
    tf32gemm<true, false><<<gemm_grid, 256, GEMM_SMEM>>>(
        p_layers, NL * NH, NL * NH, nullptr, fc2_w, fc2_b, p_local2, NH, N_NODES);

    // --- fc1: glob = relu(evo @ fc1_w + b) ---
    tf32gemm<true, false><<<gemm_grid, 256, GEMM_SMEM>>>(
        evo, EVO, EVO, nullptr, fc1_w, fc1_b, p_glob, NH, N_NODES);

    // --- fc3 (fused concat): out = relu([glob | local2] @ fc3_w + b) ---
    tf32gemm<true, true><<<gemm_grid, 256, GEMM_SMEM>>>(
        p_glob, NH, 2 * NH, p_local2, fc3_w, fc3_b, out, NH, N_NODES);
}

// round 9
// speedup vs baseline: 1.0854x; 1.0854x over previous
#include <cuda_runtime.h>
#include <cuda_bf16.h>
#include <cstddef>
#include <cstdint>

// ---------------- Problem constants (fixed by the reference) ----------------
#define N_NODES 50000
#define E_EDGES 800000
#define NFEAT   512
#define NH      256
#define NL      4
#define EVO     1024

// ---------------- Device-global scratch (no allocations allowed) ------------
__device__ float g_local0[(size_t)N_NODES * NH];          // relu(x @ fc0), tf32-rounded
__device__ float g_h[(size_t)N_NODES * NH];               // conv dense transform (fp32)
__device__ float g_layers[(size_t)N_NODES * NL * NH];     // spmm outputs, tf32-rounded
__device__ float g_glob[(size_t)N_NODES * NH];            // relu(evo @ fc1), tf32-rounded
__device__ float g_local2[(size_t)N_NODES * NH];          // relu(layers @ fc2), tf32-rounded

// Pre-transposed + tf32-rounded weights: W^T stored [256][K], k contiguous.
//  fc0: off 0        (256 x 512)
//  conv i: off 131072 + i*65536 (256 x 256)
//  fc1: off 393216   (256 x 1024)
//  fc2: off 655360   (256 x 1024)
//  fc3: off 917504   (256 x 512)
__device__ float g_wt[1048576];

__device__ int   g_counts[N_NODES];
__device__ int   g_rowptr[N_NODES + 1];
__device__ int   g_cursor[N_NODES];
__device__ int   g_colidx[E_EDGES];
__device__ float g_vals[E_EDGES];

// ---------------- tf32 helpers ----------------------------------------------
__device__ __forceinline__ uint32_t f2tf32(float x) {
    uint32_t u;
    asm("cvt.rna.tf32.f32 %0, %1;" : "=r"(u) : "f"(x));
    return u;
}
__device__ __forceinline__ float f2tf32f(float x) {
    return __uint_as_float(f2tf32(x));
}

// ---------------- Weight prep: transpose + round to tf32 --------------------
__global__ __launch_bounds__(256) void k_prep_w(
    const float* __restrict__ fc0w, const float* __restrict__ convw,
    const float* __restrict__ fc1w, const float* __restrict__ fc2w,
    const float* __restrict__ fc3w)
{
    const int i = blockIdx.x * 256 + threadIdx.x;         // 4096 blocks
    float v;
    if (i < 131072)      { int n = i >> 9, k = i & 511;   v = fc0w[k * 256 + n]; }
    else if (i < 393216) { int j = i - 131072; int m = j >> 16; int r = j & 65535;
                           int n = r >> 8, k = r & 255;   v = convw[m * 65536 + k * 256 + n]; }
    else if (i < 655360) { int j = i - 393216; int n = j >> 10, k = j & 1023;
                           v = fc1w[k * 256 + n]; }
    else if (i < 917504) { int j = i - 655360; int n = j >> 10, k = j & 1023;
                           v = fc2w[k * 256 + n]; }
    else                 { int j = i - 917504; int n = j >> 9, k = j & 511;
                           v = fc3w[k * 256 + n]; }
    g_wt[i] = f2tf32f(v);
}

// ---------------- CSR build kernels ----------------------------------------
__global__ void k_zero_counts() {
    int i = blockIdx.x * blockDim.x + threadIdx.x;
    if (i < N_NODES) g_counts[i] = 0;
}

__global__ void k_hist(const int* __restrict__ dst) {
    int e = blockIdx.x * blockDim.x + threadIdx.x;
    if (e < E_EDGES) atomicAdd(&g_counts[dst[e]], 1);
}

__global__ void k_scan() {
    __shared__ int warp_sums[32];
    __shared__ int s_carry;
    const int t = threadIdx.x, lane = t & 31, wid = t >> 5;
    if (t == 0) s_carry = 0;
    __syncthreads();
    for (int base = 0; base < N_NODES; base += 1024) {
        const int i = base + t;
        const int v = (i < N_NODES) ? g_counts[i] : 0;
        int x = v;
#pragma unroll
        for (int d = 1; d < 32; d <<= 1) {
            int y = __shfl_up_sync(0xFFFFFFFFu, x, d);
            if (lane >= d) x += y;
        }
        if (lane == 31) warp_sums[wid] = x;
        __syncthreads();
        if (wid == 0) {
            int w = warp_sums[lane];
            int ws = w;
#pragma unroll
            for (int d = 1; d < 32; d <<= 1) {
                int y = __shfl_up_sync(0xFFFFFFFFu, ws, d);
                if (lane >= d) ws += y;
            }
            warp_sums[lane] = ws - w;
        }
        __syncthreads();
        const int ex = x - v + warp_sums[wid];
        const int carry = s_carry;
        if (i < N_NODES) {
            g_rowptr[i] = carry + ex;
            g_cursor[i] = carry + ex;
        }
        __syncthreads();
        if (t == 1023) s_carry = carry + ex + v;
        __syncthreads();
    }
    if (threadIdx.x == 0) g_rowptr[N_NODES] = s_carry;
}

__global__ void k_scatter(const int* __restrict__ src, const int* __restrict__ dst,
                          const float* __restrict__ w) {
    int e = blockIdx.x * blockDim.x + threadIdx.x;
    if (e < E_EDGES) {
        int d = dst[e];
        int pos = atomicAdd(&g_cursor[d], 1);
        g_colidx[pos] = src[e];
        g_vals[pos]   = w[e];
    }
}

// ---------------- TF32 tensor-core GEMM: ldmatrix + cp.async 3-stage --------
// C[M,256] = A[M,K] @ Bt^T (+bias)(+relu)(+round), optional concat-A2 at k=256.
// Bt = pre-transposed tf32 weights [256][K], k contiguous.
// BM=128, BN=128, BK=32, 256 threads = 8 warps (2m x 4n), warp tile 64x32.
// A smem [m][k] stride 36; B smem [n][k] stride 36 (both ldmatrix conflict-free).

__device__ __forceinline__ void mma_tf32(float* d, const uint32_t* a, const uint32_t* b) {
    asm volatile(
        "mma.sync.aligned.m16n8k8.row.col.f32.tf32.tf32.f32 "
        "{%0,%1,%2,%3}, {%4,%5,%6,%7}, {%8,%9}, {%0,%1,%2,%3};\n"
        : "+f"(d[0]), "+f"(d[1]), "+f"(d[2]), "+f"(d[3])
        : "r"(a[0]), "r"(a[1]), "r"(a[2]), "r"(a[3]), "r"(b[0]), "r"(b[1]));
}

__device__ __forceinline__ void ldsm4(uint32_t& r0, uint32_t& r1, uint32_t& r2, uint32_t& r3,
                                      uint32_t addr) {
    asm volatile("ldmatrix.sync.aligned.m8n8.x4.shared.b16 {%0,%1,%2,%3}, [%4];"
                 : "=r"(r0), "=r"(r1), "=r"(r2), "=r"(r3) : "r"(addr));
}

__device__ __forceinline__ void cp16(uint32_t dst_s, const void* src, bool valid) {
    int sz = valid ? 16 : 0;
    asm volatile("cp.async.cg.shared.global [%0], [%1], 16, %2;\n"
                 :: "r"(dst_s), "l"(src), "r"(sz));
}

#define GEMM_BM 128
#define GEMM_BN 128
#define GEMM_BK 32
#define GEMM_PA 36          // stride mod 32 = 4 -> ldmatrix banks 4r+k: conflict-free
#define GEMM_PB 36
#define GEMM_STAGES 3
#define GEMM_STG_U32 (GEMM_BM * GEMM_PA + GEMM_BN * GEMM_PB)
#define GEMM_SMEM (GEMM_STAGES * GEMM_STG_U32 * 4)

template <bool RELU, bool CONCAT, bool CVT_A, bool ROUND>
__global__ __launch_bounds__(256, 2) void tf32gemm(
    const float* __restrict__ A, int lda, int K,
    const float* __restrict__ A2,           // CONCAT: second A at k>=256 (lda=256)
    const float* __restrict__ Bt,           // [256][K] tf32, k contiguous
    const float* __restrict__ bias,         // may be nullptr
    float* __restrict__ C, int ldc, int M)
{
    constexpr int BM = GEMM_BM, BK = GEMM_BK;
    constexpr int PA = GEMM_PA, PB = GEMM_PB;
    extern __shared__ float dynsmem[];

    const int t    = threadIdx.x;
    const int lane = t & 31;
    const int warp = t >> 5;
    const int row0 = blockIdx.y * BM;
    const int col0 = blockIdx.x * GEMM_BN;
    const int m0w  = (warp & 1) * 64;
    const int n0w  = (warp >> 1) * 32;
    const int g    = lane >> 2;
    const int q    = lane & 3;

    const uint32_t smem_u = (uint32_t)__cvta_generic_to_shared(dynsmem);

    float acc[4][4][4];
#pragma unroll
    for (int mi = 0; mi < 4; mi++)
#pragma unroll
        for (int ni = 0; ni < 4; ni++)
#pragma unroll
            for (int r = 0; r < 4; r++) acc[mi][ni][r] = 0.f;

    // cp.async loader coords
    // A: f = t + i*256 -> row = t>>3 + i*32, kc = (t&7)*4   (128 rows x 32 k)
    const int ar0 = t >> 3;
    const int akq = (t & 7) * 4;
    // B: f = t + i*256 -> row = t>>3 + i*32, kc = (t&7)*4   (128 rows x 32 k)
    const int br0 = t >> 3;
    const int bkc = (t & 7) * 4;

    // ldmatrix per-lane byte offsets (within a stage)
    // A x4 tile at (m0w + mi*16, kk): lanes 0-15 rows +0..15 @k, 16-31 rows +0..15 @k+4
    const int a_lm = ((m0w + (lane & 15)) * PA + (lane >> 4) * 4) * 4;
    // B x4: ts = lane>>3: rowgrp (ts>>1)*8, k half (ts&1)*4
    const int ts = lane >> 3, rowin = lane & 7;
    const int b_lm = ((n0w + (ts >> 1) * 8 + rowin) * PB + (ts & 1) * 4) * 4;

    auto issue = [&](int buf, int stage_idx) {
        const int k0 = stage_idx * BK;
        const uint32_t as_u = smem_u + (uint32_t)(buf * GEMM_STG_U32) * 4u;
        const uint32_t bs_u = as_u + (uint32_t)(BM * PA) * 4u;
        const float* Asel = A;
        int kbase = k0;
        if (CONCAT && k0 >= 256) { Asel = A2; kbase = k0 - 256; }
#pragma unroll
        for (int i = 0; i < 4; i++) {
            const int row = ar0 + i * 32;
            const bool valid = (row0 + row) < M;
            const int rclamp = valid ? (row0 + row) : (M - 1);
            cp16(as_u + (uint32_t)(row * PA + akq) * 4u,
                 Asel + (size_t)rclamp * lda + kbase + akq, valid);
        }
        // B: full 128 x 32 tile = 1024 chunks of 16B, 4 per thread
#pragma unroll
        for (int i = 0; i < 4; i++) {
            const int row = br0 + i * 32;
            cp16(bs_u + (uint32_t)(row * PB + bkc) * 4u,
                 Bt + (size_t)(col0 + row) * K + k0 + bkc, true);
        }
    };

    auto compute = [&](int buf) {
        const uint32_t as_u = smem_u + (uint32_t)(buf * GEMM_STG_U32) * 4u;
        const uint32_t bs_u = as_u + (uint32_t)(BM * PA) * 4u;
#pragma unroll
        for (int kk = 0; kk < BK; kk += 8) {
            uint32_t a[4][4], b[4][2];
#pragma unroll
            for (int mi = 0; mi < 4; mi++)
                ldsm4(a[mi][0], a[mi][1], a[mi][2], a[mi][3],
                      as_u + (uint32_t)(a_lm + (mi * 16 * PA + kk) * 4));
            if (CVT_A) {
#pragma unroll
                for (int mi = 0; mi < 4; mi++)
#pragma unroll
                    for (int r = 0; r < 4; r++)
                        a[mi][r] = f2tf32(__uint_as_float(a[mi][r]));
            }
            ldsm4(b[0][0], b[0][1], b[1][0], b[1][1],
                  bs_u + (uint32_t)(b_lm + kk * 4));
            ldsm4(b[2][0], b[2][1], b[3][0], b[3][1],
                  bs_u + (uint32_t)(b_lm + (16 * PB + kk) * 4));
#pragma unroll
            for (int mi = 0; mi < 4; mi++)
#pragma unroll
                for (int ni = 0; ni < 4; ni++)
                    mma_tf32(acc[mi][ni], a[mi], b[ni]);
        }
    };

    const int nk = K / BK;

#pragma unroll
    for (int s = 0; s < GEMM_STAGES - 1; s++) {
        if (s < nk) issue(s, s);
        asm volatile("cp.async.commit_group;\n");
    }

    for (int it = 0; it < nk; it++) {
        asm volatile("cp.async.wait_group %0;\n" :: "n"(GEMM_STAGES - 2));
        __syncthreads();
        const int nxt = it + GEMM_STAGES - 1;
        if (nxt < nk) issue(nxt % GEMM_STAGES, nxt);
        asm volatile("cp.async.commit_group;\n");
        compute(it % GEMM_STAGES);
    }

    // Epilogue: c0,c1 at (row g, col 2q,2q+1); c2,c3 at (row g+8)
#pragma unroll
    for (int mi = 0; mi < 4; mi++) {
        const int r0 = row0 + m0w + mi * 16 + g;
        const int r1 = r0 + 8;
#pragma unroll
        for (int ni = 0; ni < 4; ni++) {
            const int c = col0 + n0w + ni * 8 + q * 2;
            float bx = 0.f, by = 0.f;
            if (bias) { bx = bias[c]; by = bias[c + 1]; }
#pragma unroll
            for (int half = 0; half < 2; half++) {
                const int r = half ? r1 : r0;
                if (r < M) {
                    float vx = acc[mi][ni][half * 2 + 0] + bx;
                    float vy = acc[mi][ni][half * 2 + 1] + by;
                    if (RELU) { vx = fmaxf(vx, 0.f); vy = fmaxf(vy, 0.f); }
                    if (ROUND) { vx = f2tf32f(vx); vy = f2tf32f(vy); }
                    *(float2*)(C + (size_t)r * ldc + c) = make_float2(vx, vy);
                }
            }
        }
    }
}

// ---------------- SpMM + ReLU (float4, 4 rows per CTA, 4-way unroll) --------
// Output rounded to tf32 (it is consumed as GEMM A without further cvt).
__global__ __launch_bounds__(256) void k_spmm_relu(const float* __restrict__ h, int layer) {
    const int sub = threadIdx.x >> 6;
    const int f4  = threadIdx.x & 63;
    const int d   = blockIdx.x * 4 + sub;
    const int beg = g_rowptr[d];
    const int end = g_rowptr[d + 1];
    const float4* h4 = (const float4*)h;
    float4 acc = make_float4(0.f, 0.f, 0.f, 0.f);

    int k = beg;
    for (; k + 4 <= end; k += 4) {
        const int   s0 = g_colidx[k    ], s1 = g_colidx[k + 1];
        const int   s2 = g_colidx[k + 2], s3 = g_colidx[k + 3];
        const float w0 = g_vals[k    ], w1 = g_vals[k + 1];
        const float w2 = g_vals[k + 2], w3 = g_vals[k + 3];
        float4 v0 = h4[(size_t)s0 * 64 + f4];
        float4 v1 = h4[(size_t)s1 * 64 + f4];
        float4 v2 = h4[(size_t)s2 * 64 + f4];
        float4 v3 = h4[(size_t)s3 * 64 + f4];
        acc.x += w0 * v0.x; acc.y += w0 * v0.y; acc.z += w0 * v0.z; acc.w += w0 * v0.w;
        acc.x += w1 * v1.x; acc.y += w1 * v1.y; acc.z += w1 * v1.z; acc.w += w1 * v1.w;
        acc.x += w2 * v2.x; acc.y += w2 * v2.y; acc.z += w2 * v2.z; acc.w += w2 * v2.w;
        acc.x += w3 * v3.x; acc.y += w3 * v3.y; acc.z += w3 * v3.z; acc.w += w3 * v3.w;
    }
    for (; k < end; k++) {
        const int   s = g_colidx[k];
        const float w = g_vals[k];
        float4 v = h4[(size_t)s * 64 + f4];
        acc.x += w * v.x; acc.y += w * v.y; acc.z += w * v.z; acc.w += w * v.w;
    }
    float4 r = make_float4(f2tf32f(fmaxf(acc.x, 0.f)), f2tf32f(fmaxf(acc.y, 0.f)),
                           f2tf32f(fmaxf(acc.z, 0.f)), f2tf32f(fmaxf(acc.w, 0.f)));
    ((float4*)g_layers)[(size_t)d * (NL * NH / 4) + layer * 64 + f4] = r;
}

// ---------------- Launch ----------------------------------------------------
extern "C" void kernel_launch(void* const* d_in, const int* in_sizes, int n_in,
                              void* d_out, int out_size)
{
    const float* x        = (const float*)d_in[0];   // [N, 512]
    const float* evo      = (const float*)d_in[1];   // [N, 1024]
    const int*   esrc     = (const int*)  d_in[2];   // [E]
    const int*   edst     = (const int*)  d_in[3];   // [E]
    const float* ew       = (const float*)d_in[4];   // [E]
    const float* conv_w   = (const float*)d_in[5];   // [4, 256, 256]
    const float* fc0_w    = (const float*)d_in[6];   // [512, 256]
    const float* fc0_b    = (const float*)d_in[7];
    const float* fc1_w    = (const float*)d_in[8];   // [1024, 256]
    const float* fc1_b    = (const float*)d_in[9];
    const float* fc2_w    = (const float*)d_in[10];  // [1024, 256]
    const float* fc2_b    = (const float*)d_in[11];
    const float* fc3_w    = (const float*)d_in[12];  // [512, 256]
    const float* fc3_b    = (const float*)d_in[13];
    float* out = (float*)d_out;

    float *p_local0, *p_h, *p_layers, *p_glob, *p_local2, *p_wt;
    cudaGetSymbolAddress((void**)&p_local0, g_local0);
    cudaGetSymbolAddress((void**)&p_h,      g_h);
    cudaGetSymbolAddress((void**)&p_layers, g_layers);
    cudaGetSymbolAddress((void**)&p_glob,   g_glob);
    cudaGetSymbolAddress((void**)&p_local2, g_local2);
    cudaGetSymbolAddress((void**)&p_wt,     g_wt);

    const float* wt_fc0  = p_wt;             // [256][512]
    const float* wt_conv = p_wt + 131072;    // [4][256][256]
    const float* wt_fc1  = p_wt + 393216;    // [256][1024]
    const float* wt_fc2  = p_wt + 655360;    // [256][1024]
    const float* wt_fc3  = p_wt + 917504;    // [256][512]

    cudaFuncSetAttribute(tf32gemm<true,  false, true,  true >,
                         cudaFuncAttributeMaxDynamicSharedMemorySize, GEMM_SMEM);
    cudaFuncSetAttribute(tf32gemm<false, false, false, false>,
                         cudaFuncAttributeMaxDynamicSharedMemorySize, GEMM_SMEM);
    cudaFuncSetAttribute(tf32gemm<true,  false, false, true >,
                         cudaFuncAttributeMaxDynamicSharedMemorySize, GEMM_SMEM);
    cudaFuncSetAttribute(tf32gemm<true,  true,  false, false>,
                         cudaFuncAttributeMaxDynamicSharedMemorySize, GEMM_SMEM);

    const dim3 gemm_grid(2, (N_NODES + 127) / 128);

    // Launch order keeps the conv0 GEMM at position 3 for ncu (-s 5).
    // (pos 0) weight transpose + tf32 round
    k_prep_w<<<4096, 256>>>(fc0_w, conv_w, fc1_w, fc2_w, fc3_w);
    // (pos 1) fc0: local0 = round(relu(x @ fc0 + b))
    tf32gemm<true, false, true, true><<<gemm_grid, 256, GEMM_SMEM>>>(
        x, NFEAT, NFEAT, nullptr, wt_fc0, fc0_b, p_local0, NH, N_NODES);
    // (pos 2)
    k_zero_counts<<<(N_NODES + 255) / 256, 256>>>();
    // (pos 3) conv0 dense transform  <-- ncu capture target
    tf32gemm<false, false, false, false><<<gemm_grid, 256, GEMM_SMEM>>>(
        p_local0, NH, NH, nullptr, wt_conv, nullptr, p_h, NH, N_NODES);
    // (pos 4,5,6) CSR build
    k_hist<<<E_EDGES / 256, 256>>>(edst);
    k_scan<<<1, 1024>>>();
    k_scatter<<<E_EDGES / 256, 256>>>(esrc, edst, ew);
    // (pos 7) spmm layer 0
    k_spmm_relu<<<N_NODES / 4, 256>>>(p_h, 0);

    // conv layers 1..3
    for (int i = 1; i < NL; i++) {
        tf32gemm<false, false, false, false><<<gemm_grid, 256, GEMM_SMEM>>>(
            p_layers + (i - 1) * NH, NL * NH, NH,
            nullptr, wt_conv + (size_t)i * NH * NH, nullptr, p_h, NH, N_NODES);
        k_spmm_relu<<<N_NODES / 4, 256>>>(p_h, i);
    }

    // fc2: local2 = round(relu(layers @ fc2 + b))
    tf32gemm<true, false, false, true><<<gemm_grid, 256, GEMM_SMEM>>>(
        p_layers, NL * NH, NL * NH, nullptr, wt_fc2, fc2_b, p_local2, NH, N_NODES);

    // fc1: glob = round(relu(evo @ fc1 + b))
    tf32gemm<true, false, true, true><<<gemm_grid, 256, GEMM_SMEM>>>(
        evo, EVO, EVO, nullptr, wt_fc1, fc1_b, p_glob, NH, N_NODES);

    // fc3 (fused concat): out = relu([glob | local2] @ fc3 + b), full fp32 out
    tf32gemm<true, true, false, false><<<gemm_grid, 256, GEMM_SMEM>>>(
        p_glob, NH, 2 * NH, p_local2, wt_fc3, fc3_b, out, NH, N_NODES);
}

// round 10
// speedup vs baseline: 1.1270x; 1.0383x over previous
#include <cuda_runtime.h>
#include <cuda_fp16.h>
#include <cstddef>
#include <cstdint>

// ---------------- Problem constants (fixed by the reference) ----------------
#define N_NODES 50000
#define E_EDGES 800000
#define NFEAT   512
#define NH      256
#define NL      4
#define EVO     1024

// ---------------- Device-global scratch (no allocations allowed) ------------
__device__ float  g_local0[(size_t)N_NODES * NH];         // relu(x @ fc0), tf32-rounded
__device__ __half g_h[(size_t)N_NODES * NH];              // conv dense transform (fp16)
__device__ float  g_layers[(size_t)N_NODES * NL * NH];    // spmm outputs, tf32-rounded
__device__ float  g_glob[(size_t)N_NODES * NH];           // relu(evo @ fc1), tf32-rounded
__device__ float  g_local2[(size_t)N_NODES * NH];         // relu(layers @ fc2), tf32-rounded

// Pre-transposed + tf32-rounded weights: W^T stored [256][K], k contiguous.
__device__ float g_wt[1048576];

__device__ int   g_counts[N_NODES];
__device__ int   g_rowptr[N_NODES + 1];
__device__ int   g_cursor[N_NODES];
__device__ int   g_colidx[E_EDGES];
__device__ float g_vals[E_EDGES];

// ---------------- tf32 helpers ----------------------------------------------
__device__ __forceinline__ uint32_t f2tf32(float x) {
    uint32_t u;
    asm("cvt.rna.tf32.f32 %0, %1;" : "=r"(u) : "f"(x));
    return u;
}
__device__ __forceinline__ float f2tf32f(float x) {
    return __uint_as_float(f2tf32(x));
}

// ---------------- Weight prep: transpose + round to tf32 --------------------
__global__ __launch_bounds__(256) void k_prep_w(
    const float* __restrict__ fc0w, const float* __restrict__ convw,
    const float* __restrict__ fc1w, const float* __restrict__ fc2w,
    const float* __restrict__ fc3w)
{
    const int i = blockIdx.x * 256 + threadIdx.x;
    float v;
    if (i < 131072)      { int n = i >> 9, k = i & 511;   v = fc0w[k * 256 + n]; }
    else if (i < 393216) { int j = i - 131072; int m = j >> 16; int r = j & 65535;
                           int n = r >> 8, k = r & 255;   v = convw[m * 65536 + k * 256 + n]; }
    else if (i < 655360) { int j = i - 393216; int n = j >> 10, k = j & 1023;
                           v = fc1w[k * 256 + n]; }
    else if (i < 917504) { int j = i - 655360; int n = j >> 10, k = j & 1023;
                           v = fc2w[k * 256 + n]; }
    else                 { int j = i - 917504; int n = j >> 9, k = j & 511;
                           v = fc3w[k * 256 + n]; }
    g_wt[i] = f2tf32f(v);
}

// ---------------- CSR build kernels ----------------------------------------
__global__ void k_zero_counts() {
    int i = blockIdx.x * blockDim.x + threadIdx.x;
    if (i < N_NODES) g_counts[i] = 0;
}

__global__ void k_hist(const int* __restrict__ dst) {
    int e = blockIdx.x * blockDim.x + threadIdx.x;
    if (e < E_EDGES) atomicAdd(&g_counts[dst[e]], 1);
}

__global__ void k_scan() {
    __shared__ int warp_sums[32];
    __shared__ int s_carry;
    const int t = threadIdx.x, lane = t & 31, wid = t >> 5;
    if (t == 0) s_carry = 0;
    __syncthreads();
    for (int base = 0; base < N_NODES; base += 1024) {
        const int i = base + t;
        const int v = (i < N_NODES) ? g_counts[i] : 0;
        int x = v;
#pragma unroll
        for (int d = 1; d < 32; d <<= 1) {
            int y = __shfl_up_sync(0xFFFFFFFFu, x, d);
            if (lane >= d) x += y;
        }
        if (lane == 31) warp_sums[wid] = x;
        __syncthreads();
        if (wid == 0) {
            int w = warp_sums[lane];
            int ws = w;
#pragma unroll
            for (int d = 1; d < 32; d <<= 1) {
                int y = __shfl_up_sync(0xFFFFFFFFu, ws, d);
                if (lane >= d) ws += y;
            }
            warp_sums[lane] = ws - w;
        }
        __syncthreads();
        const int ex = x - v + warp_sums[wid];
        const int carry = s_carry;
        if (i < N_NODES) {
            g_rowptr[i] = carry + ex;
            g_cursor[i] = carry + ex;
        }
        __syncthreads();
        if (t == 1023) s_carry = carry + ex + v;
        __syncthreads();
    }
    if (threadIdx.x == 0) g_rowptr[N_NODES] = s_carry;
}

__global__ void k_scatter(const int* __restrict__ src, const int* __restrict__ dst,
                          const float* __restrict__ w) {
    int e = blockIdx.x * blockDim.x + threadIdx.x;
    if (e < E_EDGES) {
        int d = dst[e];
        int pos = atomicAdd(&g_cursor[d], 1);
        g_colidx[pos] = src[e];
        g_vals[pos]   = w[e];
    }
}

// ---------------- TF32 tensor-core GEMM: ldmatrix + cp.async 3-stage --------
// C[M,256] = A[M,K] @ Bt^T (+bias)(+relu)(+round | half-out), concat-A2 option.

__device__ __forceinline__ void mma_tf32(float* d, const uint32_t* a, const uint32_t* b) {
    asm volatile(
        "mma.sync.aligned.m16n8k8.row.col.f32.tf32.tf32.f32 "
        "{%0,%1,%2,%3}, {%4,%5,%6,%7}, {%8,%9}, {%0,%1,%2,%3};\n"
        : "+f"(d[0]), "+f"(d[1]), "+f"(d[2]), "+f"(d[3])
        : "r"(a[0]), "r"(a[1]), "r"(a[2]), "r"(a[3]), "r"(b[0]), "r"(b[1]));
}

__device__ __forceinline__ void ldsm4(uint32_t& r0, uint32_t& r1, uint32_t& r2, uint32_t& r3,
                                      uint32_t addr) {
    asm volatile("ldmatrix.sync.aligned.m8n8.x4.shared.b16 {%0,%1,%2,%3}, [%4];"
                 : "=r"(r0), "=r"(r1), "=r"(r2), "=r"(r3) : "r"(addr));
}

__device__ __forceinline__ void cp16(uint32_t dst_s, const void* src, bool valid) {
    int sz = valid ? 16 : 0;
    asm volatile("cp.async.cg.shared.global [%0], [%1], 16, %2;\n"
                 :: "r"(dst_s), "l"(src), "r"(sz));
}

#define GEMM_BM 128
#define GEMM_BN 128
#define GEMM_BK 32
#define GEMM_PA 36
#define GEMM_PB 36
#define GEMM_STAGES 3
#define GEMM_STG_U32 (GEMM_BM * GEMM_PA + GEMM_BN * GEMM_PB)
#define GEMM_SMEM (GEMM_STAGES * GEMM_STG_U32 * 4)

template <bool RELU, bool CONCAT, bool CVT_A, bool ROUND, bool OUT_HALF>
__global__ __launch_bounds__(256, 2) void tf32gemm(
    const float* __restrict__ A, int lda, int K,
    const float* __restrict__ A2,           // CONCAT: second A at k>=256 (lda=256)
    const float* __restrict__ Bt,           // [256][K] tf32, k contiguous
    const float* __restrict__ bias,         // may be nullptr
    float* __restrict__ C, int ldc, int M)  // OUT_HALF: C reinterpreted as __half*
{
    constexpr int BM = GEMM_BM, BK = GEMM_BK;
    constexpr int PA = GEMM_PA, PB = GEMM_PB;
    extern __shared__ float dynsmem[];

    const int t    = threadIdx.x;
    const int lane = t & 31;
    const int warp = t >> 5;
    const int row0 = blockIdx.y * BM;
    const int col0 = blockIdx.x * GEMM_BN;
    const int m0w  = (warp & 1) * 64;
    const int n0w  = (warp >> 1) * 32;
    const int g    = lane >> 2;
    const int q    = lane & 3;

    const uint32_t smem_u = (uint32_t)__cvta_generic_to_shared(dynsmem);

    float acc[4][4][4];
#pragma unroll
    for (int mi = 0; mi < 4; mi++)
#pragma unroll
        for (int ni = 0; ni < 4; ni++)
#pragma unroll
            for (int r = 0; r < 4; r++) acc[mi][ni][r] = 0.f;

    const int ar0 = t >> 3;
    const int akq = (t & 7) * 4;
    const int br0 = t >> 3;
    const int bkc = (t & 7) * 4;

    const int a_lm = ((m0w + (lane & 15)) * PA + (lane >> 4) * 4) * 4;
    const int ts = lane >> 3, rowin = lane & 7;
    const int b_lm = ((n0w + (ts >> 1) * 8 + rowin) * PB + (ts & 1) * 4) * 4;

    auto issue = [&](int buf, int stage_idx) {
        const int k0 = stage_idx * BK;
        const uint32_t as_u = smem_u + (uint32_t)(buf * GEMM_STG_U32) * 4u;
        const uint32_t bs_u = as_u + (uint32_t)(BM * PA) * 4u;
        const float* Asel = A;
        int kbase = k0;
        if (CONCAT && k0 >= 256) { Asel = A2; kbase = k0 - 256; }
#pragma unroll
        for (int i = 0; i < 4; i++) {
            const int row = ar0 + i * 32;
            const bool valid = (row0 + row) < M;
            const int rclamp = valid ? (row0 + row) : (M - 1);
            cp16(as_u + (uint32_t)(row * PA + akq) * 4u,
                 Asel + (size_t)rclamp * lda + kbase + akq, valid);
        }
#pragma unroll
        for (int i = 0; i < 4; i++) {
            const int row = br0 + i * 32;
            cp16(bs_u + (uint32_t)(row * PB + bkc) * 4u,
                 Bt + (size_t)(col0 + row) * K + k0 + bkc, true);
        }
    };

    auto compute = [&](int buf) {
        const uint32_t as_u = smem_u + (uint32_t)(buf * GEMM_STG_U32) * 4u;
        const uint32_t bs_u = as_u + (uint32_t)(BM * PA) * 4u;
#pragma unroll
        for (int kk = 0; kk < BK; kk += 8) {
            uint32_t a[4][4], b[4][2];
#pragma unroll
            for (int mi = 0; mi < 4; mi++)
                ldsm4(a[mi][0], a[mi][1], a[mi][2], a[mi][3],
                      as_u + (uint32_t)(a_lm + (mi * 16 * PA + kk) * 4));
            if (CVT_A) {
#pragma unroll
                for (int mi = 0; mi < 4; mi++)
#pragma unroll
                    for (int r = 0; r < 4; r++)
                        a[mi][r] = f2tf32(__uint_as_float(a[mi][r]));
            }
            ldsm4(b[0][0], b[0][1], b[1][0], b[1][1],
                  bs_u + (uint32_t)(b_lm + kk * 4));
            ldsm4(b[2][0], b[2][1], b[3][0], b[3][1],
                  bs_u + (uint32_t)(b_lm + (16 * PB + kk) * 4));
#pragma unroll
            for (int mi = 0; mi < 4; mi++)
#pragma unroll
                for (int ni = 0; ni < 4; ni++)
                    mma_tf32(acc[mi][ni], a[mi], b[ni]);
        }
    };

    const int nk = K / BK;

#pragma unroll
    for (int s = 0; s < GEMM_STAGES - 1; s++) {
        if (s < nk) issue(s, s);
        asm volatile("cp.async.commit_group;\n");
    }

    for (int it = 0; it < nk; it++) {
        asm volatile("cp.async.wait_group %0;\n" :: "n"(GEMM_STAGES - 2));
        __syncthreads();
        const int nxt = it + GEMM_STAGES - 1;
        if (nxt < nk) issue(nxt % GEMM_STAGES, nxt);
        asm volatile("cp.async.commit_group;\n");
        compute(it % GEMM_STAGES);
    }

    // Epilogue
#pragma unroll
    for (int mi = 0; mi < 4; mi++) {
        const int r0 = row0 + m0w + mi * 16 + g;
        const int r1 = r0 + 8;
#pragma unroll
        for (int ni = 0; ni < 4; ni++) {
            const int c = col0 + n0w + ni * 8 + q * 2;
            float bx = 0.f, by = 0.f;
            if (bias) { bx = bias[c]; by = bias[c + 1]; }
#pragma unroll
            for (int half = 0; half < 2; half++) {
                const int r = half ? r1 : r0;
                if (r < M) {
                    float vx = acc[mi][ni][half * 2 + 0] + bx;
                    float vy = acc[mi][ni][half * 2 + 1] + by;
                    if (RELU) { vx = fmaxf(vx, 0.f); vy = fmaxf(vy, 0.f); }
                    if (OUT_HALF) {
                        __half2* cp = (__half2*)((__half*)C + (size_t)r * ldc + c);
                        *cp = __floats2half2_rn(vx, vy);
                    } else {
                        if (ROUND) { vx = f2tf32f(vx); vy = f2tf32f(vy); }
                        *(float2*)(C + (size_t)r * ldc + c) = make_float2(vx, vy);
                    }
                }
            }
        }
    }
}

// ---------------- SpMM + ReLU over fp16 h ------------------------------------
// 8 rows/CTA, 32 lanes/row; each lane gathers 16B = 8 halves (feats lane*8..+7).
__device__ __forceinline__ void accum8(float* acc, uint4 v, float w) {
    float2 f0 = __half22float2(*(__half2*)&v.x);
    float2 f1 = __half22float2(*((__half2*)&v.x + 1));
    float2 f2 = __half22float2(*(__half2*)&v.z);
    float2 f3 = __half22float2(*((__half2*)&v.z + 1));
    acc[0] += w * f0.x; acc[1] += w * f0.y;
    acc[2] += w * f1.x; acc[3] += w * f1.y;
    acc[4] += w * f2.x; acc[5] += w * f2.y;
    acc[6] += w * f3.x; acc[7] += w * f3.y;
}

__global__ __launch_bounds__(256) void k_spmm_relu(const __half* __restrict__ h, int layer) {
    const int sub  = threadIdx.x >> 5;         // 0..7 : row within block
    const int lane = threadIdx.x & 31;         // 32 lanes x 8 halves = 256 feats
    const int d    = blockIdx.x * 8 + sub;     // 6250 * 8 = 50000 exact
    const int beg  = g_rowptr[d];
    const int end  = g_rowptr[d + 1];
    const uint4* h16 = (const uint4*)h;        // 32 chunks of 16B per row
    float acc[8] = {0.f, 0.f, 0.f, 0.f, 0.f, 0.f, 0.f, 0.f};

    int k = beg;
    for (; k + 2 <= end; k += 2) {
        const int   s0 = g_colidx[k], s1 = g_colidx[k + 1];
        const float w0 = g_vals[k],  w1 = g_vals[k + 1];
        uint4 v0 = h16[(size_t)s0 * 32 + lane];
        uint4 v1 = h16[(size_t)s1 * 32 + lane];
        accum8(acc, v0, w0);
        accum8(acc, v1, w1);
    }
    if (k < end) {
        const int   s = g_colidx[k];
        const float w = g_vals[k];
        accum8(acc, h16[(size_t)s * 32 + lane], w);
    }

    float4 r0 = make_float4(f2tf32f(fmaxf(acc[0], 0.f)), f2tf32f(fmaxf(acc[1], 0.f)),
                            f2tf32f(fmaxf(acc[2], 0.f)), f2tf32f(fmaxf(acc[3], 0.f)));
    float4 r1 = make_float4(f2tf32f(fmaxf(acc[4], 0.f)), f2tf32f(fmaxf(acc[5], 0.f)),
                            f2tf32f(fmaxf(acc[6], 0.f)), f2tf32f(fmaxf(acc[7], 0.f)));
    float* outp = g_layers + (size_t)d * (NL * NH) + layer * NH + lane * 8;
    *(float4*)outp       = r0;
    *(float4*)(outp + 4) = r1;
}

// ---------------- Launch ----------------------------------------------------
extern "C" void kernel_launch(void* const* d_in, const int* in_sizes, int n_in,
                              void* d_out, int out_size)
{
    const float* x        = (const float*)d_in[0];   // [N, 512]
    const float* evo      = (const float*)d_in[1];   // [N, 1024]
    const int*   esrc     = (const int*)  d_in[2];   // [E]
    const int*   edst     = (const int*)  d_in[3];   // [E]
    const float* ew       = (const float*)d_in[4];   // [E]
    const float* conv_w   = (const float*)d_in[5];   // [4, 256, 256]
    const float* fc0_w    = (const float*)d_in[6];   // [512, 256]
    const float* fc0_b    = (const float*)d_in[7];
    const float* fc1_w    = (const float*)d_in[8];   // [1024, 256]
    const float* fc1_b    = (const float*)d_in[9];
    const float* fc2_w    = (const float*)d_in[10];  // [1024, 256]
    const float* fc2_b    = (const float*)d_in[11];
    const float* fc3_w    = (const float*)d_in[12];  // [512, 256]
    const float* fc3_b    = (const float*)d_in[13];
    float* out = (float*)d_out;

    float *p_local0, *p_layers, *p_glob, *p_local2, *p_wt;
    __half* p_h;
    cudaGetSymbolAddress((void**)&p_local0, g_local0);
    cudaGetSymbolAddress((void**)&p_h,      g_h);
    cudaGetSymbolAddress((void**)&p_layers, g_layers);
    cudaGetSymbolAddress((void**)&p_glob,   g_glob);
    cudaGetSymbolAddress((void**)&p_local2, g_local2);
    cudaGetSymbolAddress((void**)&p_wt,     g_wt);

    const float* wt_fc0  = p_wt;             // [256][512]
    const float* wt_conv = p_wt + 131072;    // [4][256][256]
    const float* wt_fc1  = p_wt + 393216;    // [256][1024]
    const float* wt_fc2  = p_wt + 655360;    // [256][1024]
    const float* wt_fc3  = p_wt + 917504;    // [256][512]

    cudaFuncSetAttribute(tf32gemm<true,  false, true,  true,  false>,
                         cudaFuncAttributeMaxDynamicSharedMemorySize, GEMM_SMEM);
    cudaFuncSetAttribute(tf32gemm<false, false, false, false, true >,
                         cudaFuncAttributeMaxDynamicSharedMemorySize, GEMM_SMEM);
    cudaFuncSetAttribute(tf32gemm<true,  false, false, true,  false>,
                         cudaFuncAttributeMaxDynamicSharedMemorySize, GEMM_SMEM);
    cudaFuncSetAttribute(tf32gemm<true,  true,  false, false, false>,
                         cudaFuncAttributeMaxDynamicSharedMemorySize, GEMM_SMEM);

    const dim3 gemm_grid(2, (N_NODES + 127) / 128);

    // (pos 0) weight transpose + tf32 round
    k_prep_w<<<4096, 256>>>(fc0_w, conv_w, fc1_w, fc2_w, fc3_w);
    // (pos 1) fc0: local0 = round(relu(x @ fc0 + b))
    tf32gemm<true, false, true, true, false><<<gemm_grid, 256, GEMM_SMEM>>>(
        x, NFEAT, NFEAT, nullptr, wt_fc0, fc0_b, p_local0, NH, N_NODES);
    // (pos 2)
    k_zero_counts<<<(N_NODES + 255) / 256, 256>>>();
    // (pos 3) conv0 dense transform (fp16 out)  <-- ncu capture target
    tf32gemm<false, false, false, false, true><<<gemm_grid, 256, GEMM_SMEM>>>(
        p_local0, NH, NH, nullptr, wt_conv, nullptr, (float*)p_h, NH, N_NODES);
    // (pos 4,5,6) CSR build
    k_hist<<<E_EDGES / 256, 256>>>(edst);
    k_scan<<<1, 1024>>>();
    k_scatter<<<E_EDGES / 256, 256>>>(esrc, edst, ew);
    // (pos 7) spmm layer 0
    k_spmm_relu<<<N_NODES / 8, 256>>>(p_h, 0);

    // conv layers 1..3
    for (int i = 1; i < NL; i++) {
        tf32gemm<false, false, false, false, true><<<gemm_grid, 256, GEMM_SMEM>>>(
            p_layers + (i - 1) * NH, NL * NH, NH,
            nullptr, wt_conv + (size_t)i * NH * NH, nullptr, (float*)p_h, NH, N_NODES);
        k_spmm_relu<<<N_NODES / 8, 256>>>(p_h, i);
    }

    // fc2: local2 = round(relu(layers @ fc2 + b))
    tf32gemm<true, false, false, true, false><<<gemm_grid, 256, GEMM_SMEM>>>(
        p_layers, NL * NH, NL * NH, nullptr, wt_fc2, fc2_b, p_local2, NH, N_NODES);

    // fc1: glob = round(relu(evo @ fc1 + b))
    tf32gemm<true, false, true, true, false><<<gemm_grid, 256, GEMM_SMEM>>>(
        evo, EVO, EVO, nullptr, wt_fc1, fc1_b, p_glob, NH, N_NODES);

    // fc3 (fused concat): out = relu([glob | local2] @ fc3 + b), full fp32 out
    tf32gemm<true, true, false, false, false><<<gemm_grid, 256, GEMM_SMEM>>>(
        p_glob, NH, 2 * NH, p_local2, wt_fc3, fc3_b, out, NH, N_NODES);
}

// round 12
// speedup vs baseline: 1.4333x; 1.2718x over previous
#include <cuda_runtime.h>
#include <cuda_fp16.h>
#include <cstddef>
#include <cstdint>

// ---------------- Problem constants (fixed by the reference) ----------------
#define N_NODES 50000
#define E_EDGES 800000
#define NFEAT   512
#define NH      256
#define NL      4
#define EVO     1024

// ---------------- Device-global scratch (no allocations allowed) ------------
__device__ __half g_local0[(size_t)N_NODES * NH];         // relu(x @ fc0), fp16
__device__ __half g_h[(size_t)N_NODES * NH];              // conv dense transform, fp16
__device__ __half g_layers[(size_t)N_NODES * NL * NH];    // spmm outputs, fp16
__device__ __half g_glob[(size_t)N_NODES * NH];           // relu(evo @ fc1), fp16
__device__ __half g_local2[(size_t)N_NODES * NH];         // relu(layers @ fc2), fp16

// Weights, pre-transposed W^T [256][K] (k contiguous):
//  fp32(tf32-rounded) for fc0/fc1 (consumed by tf32 GEMM)
//  fp16 for conv/fc2/fc3 (consumed by fp16 GEMM)
__device__ float  g_wt[393216];    // fc0 @0 (256x512), fc1 @131072 (256x1024)
__device__ __half g_wth[655360];   // conv @0 (4x256x256), fc2 @262144, fc3 @524288

__device__ int   g_counts[N_NODES];
__device__ int   g_rowptr[N_NODES + 1];
__device__ int   g_cursor[N_NODES];
__device__ int   g_colidx[E_EDGES];
__device__ float g_vals[E_EDGES];

// ---------------- tf32 helpers ----------------------------------------------
__device__ __forceinline__ uint32_t f2tf32(float x) {
    uint32_t u;
    asm("cvt.rna.tf32.f32 %0, %1;" : "=r"(u) : "f"(x));
    return u;
}
__device__ __forceinline__ float f2tf32f(float x) {
    return __uint_as_float(f2tf32(x));
}

// ---------------- Weight prep: transpose + round -----------------------------
__global__ __launch_bounds__(256) void k_prep_w(
    const float* __restrict__ fc0w, const float* __restrict__ convw,
    const float* __restrict__ fc1w, const float* __restrict__ fc2w,
    const float* __restrict__ fc3w)
{
    const int i = blockIdx.x * 256 + threadIdx.x;         // 4096 x 256 = 1048576
    if (i < 393216) {
        float v;
        if (i < 131072) { int n = i >> 9, k = i & 511;  v = fc0w[k * 256 + n]; }
        else            { int j = i - 131072; int n = j >> 10, k = j & 1023;
                          v = fc1w[k * 256 + n]; }
        g_wt[i] = f2tf32f(v);
    } else {
        int j = i - 393216;
        float v;
        if (j < 262144)      { int m = j >> 16, r = j & 65535;
                               int n = r >> 8, k = r & 255;
                               v = convw[m * 65536 + k * 256 + n]; }
        else if (j < 524288) { int jj = j - 262144; int n = jj >> 10, k = jj & 1023;
                               v = fc2w[k * 256 + n]; }
        else                 { int jj = j - 524288; int n = jj >> 9, k = jj & 511;
                               v = fc3w[k * 256 + n]; }
        g_wth[j] = __float2half_rn(v);
    }
}

// ---------------- CSR build kernels ----------------------------------------
__global__ void k_zero_counts() {
    int i = blockIdx.x * blockDim.x + threadIdx.x;
    if (i < N_NODES) g_counts[i] = 0;
}

__global__ void k_hist(const int* __restrict__ dst) {
    int e = blockIdx.x * blockDim.x + threadIdx.x;
    if (e < E_EDGES) atomicAdd(&g_counts[dst[e]], 1);
}

__global__ void k_scan() {
    __shared__ int warp_sums[32];
    __shared__ int s_carry;
    const int t = threadIdx.x, lane = t & 31, wid = t >> 5;
    if (t == 0) s_carry = 0;
    __syncthreads();
    for (int base = 0; base < N_NODES; base += 1024) {
        const int i = base + t;
        const int v = (i < N_NODES) ? g_counts[i] : 0;
        int x = v;
#pragma unroll
        for (int d = 1; d < 32; d <<= 1) {
            int y = __shfl_up_sync(0xFFFFFFFFu, x, d);
            if (lane >= d) x += y;
        }
        if (lane == 31) warp_sums[wid] = x;
        __syncthreads();
        if (wid == 0) {
            int w = warp_sums[lane];
            int ws = w;
#pragma unroll
            for (int d = 1; d < 32; d <<= 1) {
                int y = __shfl_up_sync(0xFFFFFFFFu, ws, d);
                if (lane >= d) ws += y;
            }
            warp_sums[lane] = ws - w;
        }
        __syncthreads();
        const int ex = x - v + warp_sums[wid];
        const int carry = s_carry;
        if (i < N_NODES) {
            g_rowptr[i] = carry + ex;
            g_cursor[i] = carry + ex;
        }
        __syncthreads();
        if (t == 1023) s_carry = carry + ex + v;
        __syncthreads();
    }
    if (threadIdx.x == 0) g_rowptr[N_NODES] = s_carry;
}

__global__ void k_scatter(const int* __restrict__ src, const int* __restrict__ dst,
                          const float* __restrict__ w) {
    int e = blockIdx.x * blockDim.x + threadIdx.x;
    if (e < E_EDGES) {
        int d = dst[e];
        int pos = atomicAdd(&g_cursor[d], 1);
        g_colidx[pos] = src[e];
        g_vals[pos]   = w[e];
    }
}

// ---------------- common asm helpers ----------------------------------------
__device__ __forceinline__ void ldsm4(uint32_t& r0, uint32_t& r1, uint32_t& r2, uint32_t& r3,
                                      uint32_t addr) {
    asm volatile("ldmatrix.sync.aligned.m8n8.x4.shared.b16 {%0,%1,%2,%3}, [%4];"
                 : "=r"(r0), "=r"(r1), "=r"(r2), "=r"(r3) : "r"(addr));
}

__device__ __forceinline__ void cp16(uint32_t dst_s, const void* src, bool valid) {
    int sz = valid ? 16 : 0;
    asm volatile("cp.async.cg.shared.global [%0], [%1], 16, %2;\n"
                 :: "r"(dst_s), "l"(src), "r"(sz));
}

// ============================================================================
// TF32 GEMM (fp32 A from gmem, e.g. x / evo) -> fp16 C.   (proven R9 path)
// ============================================================================
__device__ __forceinline__ void mma_tf32(float* d, const uint32_t* a, const uint32_t* b) {
    asm volatile(
        "mma.sync.aligned.m16n8k8.row.col.f32.tf32.tf32.f32 "
        "{%0,%1,%2,%3}, {%4,%5,%6,%7}, {%8,%9}, {%0,%1,%2,%3};\n"
        : "+f"(d[0]), "+f"(d[1]), "+f"(d[2]), "+f"(d[3])
        : "r"(a[0]), "r"(a[1]), "r"(a[2]), "r"(a[3]), "r"(b[0]), "r"(b[1]));
}

#define GEMM_PA 36
#define GEMM_PB 36
#define GEMM_STG_U32 (128 * GEMM_PA + 128 * GEMM_PB)
#define GEMM_SMEM (3 * GEMM_STG_U32 * 4)

__global__ __launch_bounds__(256, 2) void tf32gemm_h(
    const float* __restrict__ A, int lda, int K,
    const float* __restrict__ Bt,           // [256][K] tf32 fp32, k contiguous
    const float* __restrict__ bias,
    __half* __restrict__ C, int ldc, int M) // relu + fp16 out
{
    constexpr int PA = GEMM_PA, PB = GEMM_PB, BK = 32;
    extern __shared__ float dynsmem[];

    const int t    = threadIdx.x;
    const int lane = t & 31;
    const int warp = t >> 5;
    const int row0 = blockIdx.y * 128;
    const int col0 = blockIdx.x * 128;
    const int m0w  = (warp & 1) * 64;
    const int n0w  = (warp >> 1) * 32;
    const int g    = lane >> 2;
    const int q    = lane & 3;

    const uint32_t smem_u = (uint32_t)__cvta_generic_to_shared(dynsmem);

    float acc[4][4][4];
#pragma unroll
    for (int mi = 0; mi < 4; mi++)
#pragma unroll
        for (int ni = 0; ni < 4; ni++)
#pragma unroll
            for (int r = 0; r < 4; r++) acc[mi][ni][r] = 0.f;

    const int ar0 = t >> 3;
    const int akq = (t & 7) * 4;
    const int br0 = t >> 3;
    const int bkc = (t & 7) * 4;

    const int a_lm = ((m0w + (lane & 15)) * PA + (lane >> 4) * 4) * 4;
    const int ts = lane >> 3, rowin = lane & 7;
    const int b_lm = ((n0w + (ts >> 1) * 8 + rowin) * PB + (ts & 1) * 4) * 4;

    auto issue = [&](int buf, int stage_idx) {
        const int k0 = stage_idx * BK;
        const uint32_t as_u = smem_u + (uint32_t)(buf * GEMM_STG_U32) * 4u;
        const uint32_t bs_u = as_u + (uint32_t)(128 * PA) * 4u;
#pragma unroll
        for (int i = 0; i < 4; i++) {
            const int row = ar0 + i * 32;
            const bool valid = (row0 + row) < M;
            const int rclamp = valid ? (row0 + row) : (M - 1);
            cp16(as_u + (uint32_t)(row * PA + akq) * 4u,
                 A + (size_t)rclamp * lda + k0 + akq, valid);
        }
#pragma unroll
        for (int i = 0; i < 4; i++) {
            const int row = br0 + i * 32;
            cp16(bs_u + (uint32_t)(row * PB + bkc) * 4u,
                 Bt + (size_t)(col0 + row) * K + k0 + bkc, true);
        }
    };

    auto compute = [&](int buf) {
        const uint32_t as_u = smem_u + (uint32_t)(buf * GEMM_STG_U32) * 4u;
        const uint32_t bs_u = as_u + (uint32_t)(128 * PA) * 4u;
#pragma unroll
        for (int kk = 0; kk < BK; kk += 8) {
            uint32_t a[4][4], b[4][2];
#pragma unroll
            for (int mi = 0; mi < 4; mi++)
                ldsm4(a[mi][0], a[mi][1], a[mi][2], a[mi][3],
                      as_u + (uint32_t)(a_lm + (mi * 16 * PA + kk) * 4));
#pragma unroll
            for (int mi = 0; mi < 4; mi++)
#pragma unroll
                for (int r = 0; r < 4; r++)
                    a[mi][r] = f2tf32(__uint_as_float(a[mi][r]));  // A is raw fp32
            ldsm4(b[0][0], b[0][1], b[1][0], b[1][1],
                  bs_u + (uint32_t)(b_lm + kk * 4));
            ldsm4(b[2][0], b[2][1], b[3][0], b[3][1],
                  bs_u + (uint32_t)(b_lm + (16 * PB + kk) * 4));
#pragma unroll
            for (int mi = 0; mi < 4; mi++)
#pragma unroll
                for (int ni = 0; ni < 4; ni++)
                    mma_tf32(acc[mi][ni], a[mi], b[ni]);
        }
    };

    const int nk = K / BK;
#pragma unroll
    for (int s = 0; s < 2; s++) {
        if (s < nk) issue(s, s);
        asm volatile("cp.async.commit_group;\n");
    }
    for (int it = 0; it < nk; it++) {
        asm volatile("cp.async.wait_group 1;\n");
        __syncthreads();
        const int nxt = it + 2;
        if (nxt < nk) issue(nxt % 3, nxt);
        asm volatile("cp.async.commit_group;\n");
        compute(it % 3);
    }

#pragma unroll
    for (int mi = 0; mi < 4; mi++) {
        const int r0 = row0 + m0w + mi * 16 + g;
        const int r1 = r0 + 8;
#pragma unroll
        for (int ni = 0; ni < 4; ni++) {
            const int c = col0 + n0w + ni * 8 + q * 2;
            const float bx = bias ? bias[c] : 0.f;
            const float by = bias ? bias[c + 1] : 0.f;
#pragma unroll
            for (int half = 0; half < 2; half++) {
                const int r = half ? r1 : r0;
                if (r < M) {
                    float vx = fmaxf(acc[mi][ni][half * 2 + 0] + bx, 0.f);
                    float vy = fmaxf(acc[mi][ni][half * 2 + 1] + by, 0.f);
                    *(__half2*)(C + (size_t)r * ldc + c) = __floats2half2_rn(vx, vy);
                }
            }
        }
    }
}

// ============================================================================
// FP16 GEMM (fp16 A + fp16 B, mma.m16n8k16, fp32 accum)
// A smem [m][k] stride 40 halves; B smem [n][k] stride 40 halves.
// ============================================================================
__device__ __forceinline__ void mma_f16(float* d, const uint32_t* a, const uint32_t* b) {
    asm volatile(
        "mma.sync.aligned.m16n8k16.row.col.f32.f16.f16.f32 "
        "{%0,%1,%2,%3}, {%4,%5,%6,%7}, {%8,%9}, {%0,%1,%2,%3};\n"
        : "+f"(d[0]), "+f"(d[1]), "+f"(d[2]), "+f"(d[3])
        : "r"(a[0]), "r"(a[1]), "r"(a[2]), "r"(a[3]), "r"(b[0]), "r"(b[1]));
}

#define G16_PA 40                      // halves; stride 80B -> ldmatrix conflict-free
#define G16_STG_H (128 * G16_PA * 2)   // halves per stage (A + B) = 10240
#define G16_SMEM (3 * G16_STG_H * 2)   // bytes = 61440

template <bool RELU, bool CONCAT, bool OUT_HALF>
__global__ __launch_bounds__(256, 2) void h16gemm(
    const __half* __restrict__ A, int lda, int K,
    const __half* __restrict__ A2,          // CONCAT: second A at k>=256 (lda=256)
    const __half* __restrict__ Bt,          // [256][K] fp16, k contiguous
    const float* __restrict__ bias,
    void* __restrict__ Cv, int ldc, int M)
{
    constexpr int PA = G16_PA, BK = 32;
    extern __shared__ __half dynsmem_h[];

    const int t    = threadIdx.x;
    const int lane = t & 31;
    const int warp = t >> 5;
    const int row0 = blockIdx.y * 128;
    const int col0 = blockIdx.x * 128;
    const int m0w  = (warp & 1) * 64;
    const int n0w  = (warp >> 1) * 32;
    const int g    = lane >> 2;
    const int q    = lane & 3;

    const uint32_t smem_u = (uint32_t)__cvta_generic_to_shared(dynsmem_h);

    float acc[4][4][4];
#pragma unroll
    for (int mi = 0; mi < 4; mi++)
#pragma unroll
        for (int ni = 0; ni < 4; ni++)
#pragma unroll
            for (int r = 0; r < 4; r++) acc[mi][ni][r] = 0.f;

    // cp.async: tile = 128 rows x 32 halves = 512 x 16B chunks; 2 per thread.
    // chunk = t + i*256: row = chunk>>2, hc = (chunk&3)*8 halves
    const int lr0 = t >> 2;                 // +64 per i
    const int lhc = (t & 3) * 8;

    // ldmatrix A: x4 16x16 tile at (m0w+mi*16, kk):
    //   lane: row = m0w + (lane&15), halfcol = kk + (lane>>4)*8
    const int a_lm = ((m0w + (lane & 15)) * PA + (lane >> 4) * 8) * 2;
    // ldmatrix B: x4 covers 2 ni tiles (16 n) x 16 k:
    //   lanes 0-7:(n+0,k+0) 8-15:(n+0,k+8) 16-23:(n+8,k+0) 24-31:(n+8,k+8)
    const int b_row = n0w + (lane & 7) + ((lane >> 4) & 1) * 8;
    const int b_lm  = (b_row * PA + ((lane >> 3) & 1) * 8) * 2;

    auto issue = [&](int buf, int stage_idx) {
        const int k0 = stage_idx * BK;
        const uint32_t as_u = smem_u + (uint32_t)(buf * G16_STG_H) * 2u;
        const uint32_t bs_u = as_u + (uint32_t)(128 * PA) * 2u;
        const __half* Asel = A;
        int kbase = k0;
        if (CONCAT && k0 >= 256) { Asel = A2; kbase = k0 - 256; }
#pragma unroll
        for (int i = 0; i < 2; i++) {
            const int row = lr0 + i * 64;
            const bool valid = (row0 + row) < M;
            const int rclamp = valid ? (row0 + row) : (M - 1);
            cp16(as_u + (uint32_t)(row * PA + lhc) * 2u,
                 Asel + (size_t)rclamp * lda + kbase + lhc, valid);
        }
#pragma unroll
        for (int i = 0; i < 2; i++) {
            const int row = lr0 + i * 64;
            cp16(bs_u + (uint32_t)(row * PA + lhc) * 2u,
                 Bt + (size_t)(col0 + row) * K + k0 + lhc, true);
        }
    };

    auto compute = [&](int buf) {
        const uint32_t as_u = smem_u + (uint32_t)(buf * G16_STG_H) * 2u;
        const uint32_t bs_u = as_u + (uint32_t)(128 * PA) * 2u;
#pragma unroll
        for (int kk = 0; kk < BK; kk += 16) {
            uint32_t a[4][4], b[4][2];
#pragma unroll
            for (int mi = 0; mi < 4; mi++)
                ldsm4(a[mi][0], a[mi][1], a[mi][2], a[mi][3],
                      as_u + (uint32_t)(a_lm + (mi * 16 * PA + kk) * 2));
#pragma unroll
            for (int p = 0; p < 2; p++) {
                uint32_t r0, r1, r2, r3;
                ldsm4(r0, r1, r2, r3,
                      bs_u + (uint32_t)(b_lm + (p * 16 * PA + kk) * 2));
                b[p * 2 + 0][0] = r0; b[p * 2 + 0][1] = r1;   // ni = 2p
                b[p * 2 + 1][0] = r2; b[p * 2 + 1][1] = r3;   // ni = 2p+1
            }
#pragma unroll
            for (int mi = 0; mi < 4; mi++)
#pragma unroll
                for (int ni = 0; ni < 4; ni++)
                    mma_f16(acc[mi][ni], a[mi], b[ni]);
        }
    };

    const int nk = K / BK;
#pragma unroll
    for (int s = 0; s < 2; s++) {
        if (s < nk) issue(s, s);
        asm volatile("cp.async.commit_group;\n");
    }
    for (int it = 0; it < nk; it++) {
        asm volatile("cp.async.wait_group 1;\n");
        __syncthreads();
        const int nxt = it + 2;
        if (nxt < nk) issue(nxt % 3, nxt);
        asm volatile("cp.async.commit_group;\n");
        compute(it % 3);
    }

    // Epilogue (C frag layout identical to k8 variant)
#pragma unroll
    for (int mi = 0; mi < 4; mi++) {
        const int r0 = row0 + m0w + mi * 16 + g;
        const int r1 = r0 + 8;
#pragma unroll
        for (int ni = 0; ni < 4; ni++) {
            const int c = col0 + n0w + ni * 8 + q * 2;
            const float bx = bias ? bias[c] : 0.f;
            const float by = bias ? bias[c + 1] : 0.f;
#pragma unroll
            for (int half = 0; half < 2; half++) {
                const int r = half ? r1 : r0;
                if (r < M) {
                    float vx = acc[mi][ni][half * 2 + 0] + bx;
                    float vy = acc[mi][ni][half * 2 + 1] + by;
                    if (RELU) { vx = fmaxf(vx, 0.f); vy = fmaxf(vy, 0.f); }
                    if (OUT_HALF) {
                        *(__half2*)((__half*)Cv + (size_t)r * ldc + c) =
                            __floats2half2_rn(vx, vy);
                    } else {
                        *(float2*)((float*)Cv + (size_t)r * ldc + c) =
                            make_float2(vx, vy);
                    }
                }
            }
        }
    }
}

// ---------------- SpMM + ReLU over fp16 h, fp16 out --------------------------
__device__ __forceinline__ void accum8(float* acc, uint4 v, float w) {
    float2 f0 = __half22float2(*(__half2*)&v.x);
    float2 f1 = __half22float2(*(__half2*)&v.y);
    float2 f2 = __half22float2(*(__half2*)&v.z);
    float2 f3 = __half22float2(*(__half2*)&v.w);
    acc[0] += w * f0.x; acc[1] += w * f0.y;
    acc[2] += w * f1.x; acc[3] += w * f1.y;
    acc[4] += w * f2.x; acc[5] += w * f2.y;
    acc[6] += w * f3.x; acc[7] += w * f3.y;
}

__global__ __launch_bounds__(256) void k_spmm_relu(const __half* __restrict__ h, int layer) {
    const int sub  = threadIdx.x >> 5;
    const int lane = threadIdx.x & 31;
    const int d    = blockIdx.x * 8 + sub;
    const int beg  = g_rowptr[d];
    const int end  = g_rowptr[d + 1];
    const uint4* h16 = (const uint4*)h;
    float acc[8] = {0.f, 0.f, 0.f, 0.f, 0.f, 0.f, 0.f, 0.f};

    int k = beg;
    for (; k + 2 <= end; k += 2) {
        const int   s0 = g_colidx[k], s1 = g_colidx[k + 1];
        const float w0 = g_vals[k],  w1 = g_vals[k + 1];
        uint4 v0 = h16[(size_t)s0 * 32 + lane];
        uint4 v1 = h16[(size_t)s1 * 32 + lane];
        accum8(acc, v0, w0);
        accum8(acc, v1, w1);
    }
    if (k < end) {
        accum8(acc, h16[(size_t)g_colidx[k] * 32 + lane], g_vals[k]);
    }

    __half2 o0 = __floats2half2_rn(fmaxf(acc[0], 0.f), fmaxf(acc[1], 0.f));
    __half2 o1 = __floats2half2_rn(fmaxf(acc[2], 0.f), fmaxf(acc[3], 0.f));
    __half2 o2 = __floats2half2_rn(fmaxf(acc[4], 0.f), fmaxf(acc[5], 0.f));
    __half2 o3 = __floats2half2_rn(fmaxf(acc[6], 0.f), fmaxf(acc[7], 0.f));
    uint4 v;
    v.x = *(uint32_t*)&o0; v.y = *(uint32_t*)&o1;
    v.z = *(uint32_t*)&o2; v.w = *(uint32_t*)&o3;
    *(uint4*)(g_layers + (size_t)d * (NL * NH) + layer * NH + lane * 8) = v;
}

// ---------------- Launch ----------------------------------------------------
extern "C" void kernel_launch(void* const* d_in, const int* in_sizes, int n_in,
                              void* d_out, int out_size)
{
    const float* x        = (const float*)d_in[0];
    const float* evo      = (const float*)d_in[1];
    const int*   esrc     = (const int*)  d_in[2];
    const int*   edst     = (const int*)  d_in[3];
    const float* ew       = (const float*)d_in[4];
    const float* conv_w   = (const float*)d_in[5];
    const float* fc0_w    = (const float*)d_in[6];
    const float* fc0_b    = (const float*)d_in[7];
    const float* fc1_w    = (const float*)d_in[8];
    const float* fc1_b    = (const float*)d_in[9];
    const float* fc2_w    = (const float*)d_in[10];
    const float* fc2_b    = (const float*)d_in[11];
    const float* fc3_w    = (const float*)d_in[12];
    const float* fc3_b    = (const float*)d_in[13];
    float* out = (float*)d_out;

    __half *p_local0, *p_h, *p_layers, *p_glob, *p_local2, *p_wth;
    float  *p_wt;
    cudaGetSymbolAddress((void**)&p_local0, g_local0);
    cudaGetSymbolAddress((void**)&p_h,      g_h);
    cudaGetSymbolAddress((void**)&p_layers, g_layers);
    cudaGetSymbolAddress((void**)&p_glob,   g_glob);
    cudaGetSymbolAddress((void**)&p_local2, g_local2);
    cudaGetSymbolAddress((void**)&p_wt,     g_wt);
    cudaGetSymbolAddress((void**)&p_wth,    g_wth);

    const float*  wt_fc0   = p_wt;               // [256][512]  fp32/tf32
    const float*  wt_fc1   = p_wt + 131072;      // [256][1024] fp32/tf32
    const __half* wth_conv = p_wth;              // [4][256][256] fp16
    const __half* wth_fc2  = p_wth + 262144;     // [256][1024] fp16
    const __half* wth_fc3  = p_wth + 524288;     // [256][512]  fp16

    cudaFuncSetAttribute(tf32gemm_h,
                         cudaFuncAttributeMaxDynamicSharedMemorySize, GEMM_SMEM);
    cudaFuncSetAttribute(h16gemm<false, false, true >,
                         cudaFuncAttributeMaxDynamicSharedMemorySize, G16_SMEM);
    cudaFuncSetAttribute(h16gemm<true,  false, true >,
                         cudaFuncAttributeMaxDynamicSharedMemorySize, G16_SMEM);
    cudaFuncSetAttribute(h16gemm<true,  true,  false>,
                         cudaFuncAttributeMaxDynamicSharedMemorySize, G16_SMEM);

    const dim3 gemm_grid(2, (N_NODES + 127) / 128);

    // (pos 0) weight prep
    k_prep_w<<<4096, 256>>>(fc0_w, conv_w, fc1_w, fc2_w, fc3_w);
    // (pos 1) fc0: local0 = fp16(relu(x @ fc0 + b))   [tf32 path]
    tf32gemm_h<<<gemm_grid, 256, GEMM_SMEM>>>(
        x, NFEAT, NFEAT, wt_fc0, fc0_b, p_local0, NH, N_NODES);
    // (pos 2)
    k_zero_counts<<<(N_NODES + 255) / 256, 256>>>();
    // (pos 3) conv0 dense transform (fp16 GEMM)  <-- ncu capture target
    h16gemm<false, false, true><<<gemm_grid, 256, G16_SMEM>>>(
        p_local0, NH, NH, nullptr, wth_conv, nullptr, p_h, NH, N_NODES);
    // (pos 4,5,6) CSR build
    k_hist<<<E_EDGES / 256, 256>>>(edst);
    k_scan<<<1, 1024>>>();
    k_scatter<<<E_EDGES / 256, 256>>>(esrc, edst, ew);
    // (pos 7) spmm layer 0
    k_spmm_relu<<<N_NODES / 8, 256>>>(p_h, 0);

    // conv layers 1..3
    for (int i = 1; i < NL; i++) {
        h16gemm<false, false, true><<<gemm_grid, 256, G16_SMEM>>>(
            p_layers + (size_t)(i - 1) * NH, NL * NH, NH,
            nullptr, wth_conv + (size_t)i * NH * NH, nullptr, p_h, NH, N_NODES);
        k_spmm_relu<<<N_NODES / 8, 256>>>(p_h, i);
    }

    // fc2: local2 = fp16(relu(layers @ fc2 + b))
    h16gemm<true, false, true><<<gemm_grid, 256, G16_SMEM>>>(
        p_layers, NL * NH, NL * NH, nullptr, wth_fc2, fc2_b, p_local2, NH, N_NODES);

    // fc1: glob = fp16(relu(evo @ fc1 + b))   [tf32 path]
    tf32gemm_h<<<gemm_grid, 256, GEMM_SMEM>>>(
        evo, EVO, EVO, wt_fc1, fc1_b, p_glob, NH, N_NODES);

    // fc3 (fused concat): out = relu([glob | local2] @ fc3 + b), fp32 out
    h16gemm<true, true, false><<<gemm_grid, 256, G16_SMEM>>>(
        p_glob, NH, 2 * NH, p_local2, wth_fc3, fc3_b, out, NH, N_NODES);
}

// round 13
// speedup vs baseline: 1.6418x; 1.1454x over previous
#include <cuda_runtime.h>
#include <cuda_fp16.h>
#include <cstddef>
#include <cstdint>

// ---------------- Problem constants (fixed by the reference) ----------------
#define N_NODES 50000
#define E_EDGES 800000
#define NFEAT   512
#define NH      256
#define NL      4
#define EVO     1024

// ---------------- Device-global scratch (no allocations allowed) ------------
__device__ __half g_xh[(size_t)N_NODES * NFEAT];          // fp16 copy of x
__device__ __half g_evoh[(size_t)N_NODES * EVO];          // fp16 copy of evo
__device__ __half g_local0[(size_t)N_NODES * NH];         // relu(x @ fc0), fp16
__device__ __half g_h[(size_t)N_NODES * NH];              // conv dense transform, fp16
__device__ __half g_layers[(size_t)N_NODES * NL * NH];    // spmm outputs, fp16
__device__ __half g_glob[(size_t)N_NODES * NH];           // relu(evo @ fc1), fp16
__device__ __half g_local2[(size_t)N_NODES * NH];         // relu(layers @ fc2), fp16

// All weights fp16, pre-transposed W^T [256][K] (k contiguous):
//  fc0 @0 (256x512), conv @131072 (4x256x256), fc1 @393216 (256x1024),
//  fc2 @655360 (256x1024), fc3 @917504 (256x512)
__device__ __half g_wth[1048576];

__device__ int   g_counts[N_NODES];
__device__ int   g_rowptr[N_NODES + 1];
__device__ int   g_cursor[N_NODES];
__device__ int   g_colidx[E_EDGES];
__device__ float g_vals[E_EDGES];

// ---------------- Weight prep: transpose + round to fp16 ---------------------
__global__ __launch_bounds__(256) void k_prep_w(
    const float* __restrict__ fc0w, const float* __restrict__ convw,
    const float* __restrict__ fc1w, const float* __restrict__ fc2w,
    const float* __restrict__ fc3w)
{
    const int i = blockIdx.x * 256 + threadIdx.x;         // 4096 x 256 = 1048576
    float v;
    if (i < 131072)      { int n = i >> 9, k = i & 511;   v = fc0w[k * 256 + n]; }
    else if (i < 393216) { int j = i - 131072; int m = j >> 16; int r = j & 65535;
                           int n = r >> 8, k = r & 255;   v = convw[m * 65536 + k * 256 + n]; }
    else if (i < 655360) { int j = i - 393216; int n = j >> 10, k = j & 1023;
                           v = fc1w[k * 256 + n]; }
    else if (i < 917504) { int j = i - 655360; int n = j >> 10, k = j & 1023;
                           v = fc2w[k * 256 + n]; }
    else                 { int j = i - 917504; int n = j >> 9, k = j & 511;
                           v = fc3w[k * 256 + n]; }
    g_wth[i] = __float2half_rn(v);
}

// ---------------- fp32 -> fp16 bulk convert (float4 per thread) -------------
__global__ __launch_bounds__(256) void k_cvt(const float* __restrict__ src,
                                             __half* __restrict__ dst) {
    const size_t i = ((size_t)blockIdx.x * 256 + threadIdx.x) * 4;
    float4 v = *(const float4*)(src + i);
    __half2 a = __floats2half2_rn(v.x, v.y);
    __half2 b = __floats2half2_rn(v.z, v.w);
    uint2 o;
    o.x = *(uint32_t*)&a; o.y = *(uint32_t*)&b;
    *(uint2*)(dst + i) = o;
}

// ---------------- CSR build kernels ----------------------------------------
__global__ void k_zero_counts() {
    int i = blockIdx.x * blockDim.x + threadIdx.x;
    if (i < N_NODES) g_counts[i] = 0;
}

__global__ void k_hist(const int* __restrict__ dst) {
    int e = blockIdx.x * blockDim.x + threadIdx.x;
    if (e < E_EDGES) atomicAdd(&g_counts[dst[e]], 1);
}

__global__ void k_scan() {
    __shared__ int warp_sums[32];
    __shared__ int s_carry;
    const int t = threadIdx.x, lane = t & 31, wid = t >> 5;
    if (t == 0) s_carry = 0;
    __syncthreads();
    for (int base = 0; base < N_NODES; base += 1024) {
        const int i = base + t;
        const int v = (i < N_NODES) ? g_counts[i] : 0;
        int x = v;
#pragma unroll
        for (int d = 1; d < 32; d <<= 1) {
            int y = __shfl_up_sync(0xFFFFFFFFu, x, d);
            if (lane >= d) x += y;
        }
        if (lane == 31) warp_sums[wid] = x;
        __syncthreads();
        if (wid == 0) {
            int w = warp_sums[lane];
            int ws = w;
#pragma unroll
            for (int d = 1; d < 32; d <<= 1) {
                int y = __shfl_up_sync(0xFFFFFFFFu, ws, d);
                if (lane >= d) ws += y;
            }
            warp_sums[lane] = ws - w;
        }
        __syncthreads();
        const int ex = x - v + warp_sums[wid];
        const int carry = s_carry;
        if (i < N_NODES) {
            g_rowptr[i] = carry + ex;
            g_cursor[i] = carry + ex;
        }
        __syncthreads();
        if (t == 1023) s_carry = carry + ex + v;
        __syncthreads();
    }
    if (threadIdx.x == 0) g_rowptr[N_NODES] = s_carry;
}

__global__ void k_scatter(const int* __restrict__ src, const int* __restrict__ dst,
                          const float* __restrict__ w) {
    int e = blockIdx.x * blockDim.x + threadIdx.x;
    if (e < E_EDGES) {
        int d = dst[e];
        int pos = atomicAdd(&g_cursor[d], 1);
        g_colidx[pos] = src[e];
        g_vals[pos]   = w[e];
    }
}

// ---------------- common asm helpers ----------------------------------------
__device__ __forceinline__ void ldsm4(uint32_t& r0, uint32_t& r1, uint32_t& r2, uint32_t& r3,
                                      uint32_t addr) {
    asm volatile("ldmatrix.sync.aligned.m8n8.x4.shared.b16 {%0,%1,%2,%3}, [%4];"
                 : "=r"(r0), "=r"(r1), "=r"(r2), "=r"(r3) : "r"(addr));
}

__device__ __forceinline__ void cp16(uint32_t dst_s, const void* src, bool valid) {
    int sz = valid ? 16 : 0;
    asm volatile("cp.async.cg.shared.global [%0], [%1], 16, %2;\n"
                 :: "r"(dst_s), "l"(src), "r"(sz));
}

// ============================================================================
// FP16 GEMM (fp16 A + fp16 B, mma.m16n8k16, fp32 accum), BK=64, 3 stages.
// A smem [m][k] stride 72 halves; B smem [n][k] stride 72 halves.
// Bank check: 72 halves = 144B; ldmatrix row r -> word-bank 4r (mod 32),
// bijective over the 8 rows of a phase -> conflict-free.
// ============================================================================
__device__ __forceinline__ void mma_f16(float* d, const uint32_t* a, const uint32_t* b) {
    asm volatile(
        "mma.sync.aligned.m16n8k16.row.col.f32.f16.f16.f32 "
        "{%0,%1,%2,%3}, {%4,%5,%6,%7}, {%8,%9}, {%0,%1,%2,%3};\n"
        : "+f"(d[0]), "+f"(d[1]), "+f"(d[2]), "+f"(d[3])
        : "r"(a[0]), "r"(a[1]), "r"(a[2]), "r"(a[3]), "r"(b[0]), "r"(b[1]));
}

#define G16_BK 64
#define G16_PA 72                       // halves; 144B stride, conflict-free
#define G16_STG_H (128 * G16_PA * 2)    // halves per stage (A + B) = 18432
#define G16_SMEM (3 * G16_STG_H * 2)    // bytes = 110592

template <bool RELU, bool CONCAT, bool OUT_HALF>
__global__ __launch_bounds__(256, 2) void h16gemm(
    const __half* __restrict__ A, int lda, int K,
    const __half* __restrict__ A2,          // CONCAT: second A at k>=256 (lda=256)
    const __half* __restrict__ Bt,          // [256][K] fp16, k contiguous
    const float* __restrict__ bias,
    void* __restrict__ Cv, int ldc, int M)
{
    constexpr int PA = G16_PA, BK = G16_BK;
    extern __shared__ __half dynsmem_h[];

    const int t    = threadIdx.x;
    const int lane = t & 31;
    const int warp = t >> 5;
    const int row0 = blockIdx.y * 128;
    const int col0 = blockIdx.x * 128;
    const int m0w  = (warp & 1) * 64;
    const int n0w  = (warp >> 1) * 32;
    const int g    = lane >> 2;
    const int q    = lane & 3;

    const uint32_t smem_u = (uint32_t)__cvta_generic_to_shared(dynsmem_h);

    float acc[4][4][4];
#pragma unroll
    for (int mi = 0; mi < 4; mi++)
#pragma unroll
        for (int ni = 0; ni < 4; ni++)
#pragma unroll
            for (int r = 0; r < 4; r++) acc[mi][ni][r] = 0.f;

    // cp.async: tile = 128 rows x 64 halves = 1024 chunks of 16B; 4 per thread.
    // chunk = t + i*256: row = chunk>>3 = t>>3 + i*32, hc = (chunk&7)*8
    const int lr0 = t >> 3;
    const int lhc = (t & 7) * 8;

    // ldmatrix A: x4 16x16 tile at (m0w+mi*16, kk)
    const int a_lm = ((m0w + (lane & 15)) * PA + (lane >> 4) * 8) * 2;
    // ldmatrix B: x4 covers 2 ni tiles (16 n) x 16 k
    const int b_row = n0w + (lane & 7) + ((lane >> 4) & 1) * 8;
    const int b_lm  = (b_row * PA + ((lane >> 3) & 1) * 8) * 2;

    auto issue = [&](int buf, int stage_idx) {
        const int k0 = stage_idx * BK;
        const uint32_t as_u = smem_u + (uint32_t)(buf * G16_STG_H) * 2u;
        const uint32_t bs_u = as_u + (uint32_t)(128 * PA) * 2u;
        const __half* Asel = A;
        int kbase = k0;
        if (CONCAT && k0 >= 256) { Asel = A2; kbase = k0 - 256; }
#pragma unroll
        for (int i = 0; i < 4; i++) {
            const int row = lr0 + i * 32;
            const bool valid = (row0 + row) < M;
            const int rclamp = valid ? (row0 + row) : (M - 1);
            cp16(as_u + (uint32_t)(row * PA + lhc) * 2u,
                 Asel + (size_t)rclamp * lda + kbase + lhc, valid);
        }
#pragma unroll
        for (int i = 0; i < 4; i++) {
            const int row = lr0 + i * 32;
            cp16(bs_u + (uint32_t)(row * PA + lhc) * 2u,
                 Bt + (size_t)(col0 + row) * K + k0 + lhc, true);
        }
    };

    auto compute = [&](int buf) {
        const uint32_t as_u = smem_u + (uint32_t)(buf * G16_STG_H) * 2u;
        const uint32_t bs_u = as_u + (uint32_t)(128 * PA) * 2u;
#pragma unroll
        for (int kk = 0; kk < BK; kk += 16) {
            uint32_t a[4][4], b[4][2];
#pragma unroll
            for (int mi = 0; mi < 4; mi++)
                ldsm4(a[mi][0], a[mi][1], a[mi][2], a[mi][3],
                      as_u + (uint32_t)(a_lm + (mi * 16 * PA + kk) * 2));
#pragma unroll
            for (int p = 0; p < 2; p++) {
                uint32_t r0, r1, r2, r3;
                ldsm4(r0, r1, r2, r3,
                      bs_u + (uint32_t)(b_lm + (p * 16 * PA + kk) * 2));
                b[p * 2 + 0][0] = r0; b[p * 2 + 0][1] = r1;
                b[p * 2 + 1][0] = r2; b[p * 2 + 1][1] = r3;
            }
#pragma unroll
            for (int mi = 0; mi < 4; mi++)
#pragma unroll
                for (int ni = 0; ni < 4; ni++)
                    mma_f16(acc[mi][ni], a[mi], b[ni]);
        }
    };

    const int nk = K / BK;
#pragma unroll
    for (int s = 0; s < 2; s++) {
        if (s < nk) issue(s, s);
        asm volatile("cp.async.commit_group;\n");
    }
    for (int it = 0; it < nk; it++) {
        asm volatile("cp.async.wait_group 1;\n");
        __syncthreads();
        const int nxt = it + 2;
        if (nxt < nk) issue(nxt % 3, nxt);
        asm volatile("cp.async.commit_group;\n");
        compute(it % 3);
    }

    // Epilogue
#pragma unroll
    for (int mi = 0; mi < 4; mi++) {
        const int r0 = row0 + m0w + mi * 16 + g;
        const int r1 = r0 + 8;
#pragma unroll
        for (int ni = 0; ni < 4; ni++) {
            const int c = col0 + n0w + ni * 8 + q * 2;
            const float bx = bias ? bias[c] : 0.f;
            const float by = bias ? bias[c + 1] : 0.f;
#pragma unroll
            for (int half = 0; half < 2; half++) {
                const int r = half ? r1 : r0;
                if (r < M) {
                    float vx = acc[mi][ni][half * 2 + 0] + bx;
                    float vy = acc[mi][ni][half * 2 + 1] + by;
                    if (RELU) { vx = fmaxf(vx, 0.f); vy = fmaxf(vy, 0.f); }
                    if (OUT_HALF) {
                        *(__half2*)((__half*)Cv + (size_t)r * ldc + c) =
                            __floats2half2_rn(vx, vy);
                    } else {
                        *(float2*)((float*)Cv + (size_t)r * ldc + c) =
                            make_float2(vx, vy);
                    }
                }
            }
        }
    }
}

// ---------------- SpMM + ReLU over fp16 h, fp16 out --------------------------
__device__ __forceinline__ void accum8(float* acc, uint4 v, float w) {
    float2 f0 = __half22float2(*(__half2*)&v.x);
    float2 f1 = __half22float2(*(__half2*)&v.y);
    float2 f2 = __half22float2(*(__half2*)&v.z);
    float2 f3 = __half22float2(*(__half2*)&v.w);
    acc[0] += w * f0.x; acc[1] += w * f0.y;
    acc[2] += w * f1.x; acc[3] += w * f1.y;
    acc[4] += w * f2.x; acc[5] += w * f2.y;
    acc[6] += w * f3.x; acc[7] += w * f3.y;
}

__global__ __launch_bounds__(256) void k_spmm_relu(const __half* __restrict__ h, int layer) {
    const int sub  = threadIdx.x >> 5;
    const int lane = threadIdx.x & 31;
    const int d    = blockIdx.x * 8 + sub;
    const int beg  = g_rowptr[d];
    const int end  = g_rowptr[d + 1];
    const uint4* h16 = (const uint4*)h;
    float acc[8] = {0.f, 0.f, 0.f, 0.f, 0.f, 0.f, 0.f, 0.f};

    int k = beg;
    for (; k + 2 <= end; k += 2) {
        const int   s0 = g_colidx[k], s1 = g_colidx[k + 1];
        const float w0 = g_vals[k],  w1 = g_vals[k + 1];
        uint4 v0 = h16[(size_t)s0 * 32 + lane];
        uint4 v1 = h16[(size_t)s1 * 32 + lane];
        accum8(acc, v0, w0);
        accum8(acc, v1, w1);
    }
    if (k < end) {
        accum8(acc, h16[(size_t)g_colidx[k] * 32 + lane], g_vals[k]);
    }

    __half2 o0 = __floats2half2_rn(fmaxf(acc[0], 0.f), fmaxf(acc[1], 0.f));
    __half2 o1 = __floats2half2_rn(fmaxf(acc[2], 0.f), fmaxf(acc[3], 0.f));
    __half2 o2 = __floats2half2_rn(fmaxf(acc[4], 0.f), fmaxf(acc[5], 0.f));
    __half2 o3 = __floats2half2_rn(fmaxf(acc[6], 0.f), fmaxf(acc[7], 0.f));
    uint4 v;
    v.x = *(uint32_t*)&o0; v.y = *(uint32_t*)&o1;
    v.z = *(uint32_t*)&o2; v.w = *(uint32_t*)&o3;
    *(uint4*)(g_layers + (size_t)d * (NL * NH) + layer * NH + lane * 8) = v;
}

// ---------------- Launch ----------------------------------------------------
extern "C" void kernel_launch(void* const* d_in, const int* in_sizes, int n_in,
                              void* d_out, int out_size)
{
    const float* x        = (const float*)d_in[0];
    const float* evo      = (const float*)d_in[1];
    const int*   esrc     = (const int*)  d_in[2];
    const int*   edst     = (const int*)  d_in[3];
    const float* ew       = (const float*)d_in[4];
    const float* conv_w   = (const float*)d_in[5];
    const float* fc0_w    = (const float*)d_in[6];
    const float* fc0_b    = (const float*)d_in[7];
    const float* fc1_w    = (const float*)d_in[8];
    const float* fc1_b    = (const float*)d_in[9];
    const float* fc2_w    = (const float*)d_in[10];
    const float* fc2_b    = (const float*)d_in[11];
    const float* fc3_w    = (const float*)d_in[12];
    const float* fc3_b    = (const float*)d_in[13];
    float* out = (float*)d_out;

    __half *p_xh, *p_evoh, *p_local0, *p_h, *p_layers, *p_glob, *p_local2, *p_wth;
    cudaGetSymbolAddress((void**)&p_xh,     g_xh);
    cudaGetSymbolAddress((void**)&p_evoh,   g_evoh);
    cudaGetSymbolAddress((void**)&p_local0, g_local0);
    cudaGetSymbolAddress((void**)&p_h,      g_h);
    cudaGetSymbolAddress((void**)&p_layers, g_layers);
    cudaGetSymbolAddress((void**)&p_glob,   g_glob);
    cudaGetSymbolAddress((void**)&p_local2, g_local2);
    cudaGetSymbolAddress((void**)&p_wth,    g_wth);

    const __half* wth_fc0  = p_wth;              // [256][512]
    const __half* wth_conv = p_wth + 131072;     // [4][256][256]
    const __half* wth_fc1  = p_wth + 393216;     // [256][1024]
    const __half* wth_fc2  = p_wth + 655360;     // [256][1024]
    const __half* wth_fc3  = p_wth + 917504;     // [256][512]

    cudaFuncSetAttribute(h16gemm<false, false, true >,
                         cudaFuncAttributeMaxDynamicSharedMemorySize, G16_SMEM);
    cudaFuncSetAttribute(h16gemm<true,  false, true >,
                         cudaFuncAttributeMaxDynamicSharedMemorySize, G16_SMEM);
    cudaFuncSetAttribute(h16gemm<true,  true,  false>,
                         cudaFuncAttributeMaxDynamicSharedMemorySize, G16_SMEM);

    const dim3 gemm_grid(2, (N_NODES + 127) / 128);

    // (pos 0) weight transpose + fp16 round
    k_prep_w<<<4096, 256>>>(fc0_w, conv_w, fc1_w, fc2_w, fc3_w);
    // (pos 1) x -> fp16  (25,600,000 / 4 / 256 = 25000 blocks)
    k_cvt<<<25000, 256>>>(x, p_xh);
    // (pos 2) fc0: local0 = fp16(relu(x_h @ fc0 + b))
    h16gemm<true, false, true><<<gemm_grid, 256, G16_SMEM>>>(
        p_xh, NFEAT, NFEAT, nullptr, wth_fc0, fc0_b, p_local0, NH, N_NODES);
    // (pos 3) conv0 dense transform  <-- ncu capture target
    h16gemm<false, false, true><<<gemm_grid, 256, G16_SMEM>>>(
        p_local0, NH, NH, nullptr, wth_conv, nullptr, p_h, NH, N_NODES);
    // CSR build
    k_zero_counts<<<(N_NODES + 255) / 256, 256>>>();
    k_hist<<<E_EDGES / 256, 256>>>(edst);
    k_scan<<<1, 1024>>>();
    k_scatter<<<E_EDGES / 256, 256>>>(esrc, edst, ew);
    // spmm layer 0
    k_spmm_relu<<<N_NODES / 8, 256>>>(p_h, 0);

    // conv layers 1..3
    for (int i = 1; i < NL; i++) {
        h16gemm<false, false, true><<<gemm_grid, 256, G16_SMEM>>>(
            p_layers + (size_t)(i - 1) * NH, NL * NH, NH,
            nullptr, wth_conv + (size_t)i * NH * NH, nullptr, p_h, NH, N_NODES);
        k_spmm_relu<<<N_NODES / 8, 256>>>(p_h, i);
    }

    // evo -> fp16  (51,200,000 / 4 / 256 = 50000 blocks)
    k_cvt<<<50000, 256>>>(evo, p_evoh);

    // fc2: local2 = fp16(relu(layers @ fc2 + b))
    h16gemm<true, false, true><<<gemm_grid, 256, G16_SMEM>>>(
        p_layers, NL * NH, NL * NH, nullptr, wth_fc2, fc2_b, p_local2, NH, N_NODES);

    // fc1: glob = fp16(relu(evo_h @ fc1 + b))
    h16gemm<true, false, true><<<gemm_grid, 256, G16_SMEM>>>(
        p_evoh, EVO, EVO, nullptr, wth_fc1, fc1_b, p_glob, NH, N_NODES);

    // fc3 (fused concat): out = relu([glob | local2] @ fc3 + b), fp32 out
    h16gemm<true, true, false><<<gemm_grid, 256, G16_SMEM>>>(
        p_glob, NH, 2 * NH, p_local2, wth_fc3, fc3_b, out, NH, N_NODES);
}